// round 7
// baseline (speedup 1.0000x reference)
#include <cuda_runtime.h>
#include <cuda_bf16.h>
#include <math.h>
#include <stdint.h>

#define NV 6890
#define MP 6912            // padded M (multiple of 256)
#define CIN 3
#define RR 5
#define AA 8
#define RA 40
#define TT 100
#define NCOL 800
#define LDA 12096          // conv A' row stride (>= 12032)
#define LDBC 896           // conv B' row stride (7*128)
#define LDAX 320           // dense A' row stride
#define LDBD 6912          // dense B' row stride (54*128)
#define KT_CONV1 384       // 3*120 padded to 64
#define KT_CONV23 12032    // 3*4000 padded to 64
#define KT_DENSE 320       // 3*100 padded to 64

// ---- scratch (device globals, zero-initialized at module load; pads stay zero) ----
__device__ float g_x[NV * TT];
__device__ __nv_bfloat16 g_A [(size_t)MP * LDA];        // tripled bf16 patch [hi,hi,lo]
__device__ __nv_bfloat16 g_B [(size_t)12096 * LDBC];    // tripled bf16 rotated weights [hi,lo,hi]
__device__ __nv_bfloat16 g_Ax[(size_t)MP * LDAX];       // tripled bf16 dense input
__device__ __nv_bfloat16 g_Bd[(size_t)KT_DENSE * LDBD]; // tripled bf16 dense weights
__device__ float g_conv[NV * NCOL];

__device__ __forceinline__ void bfsplit(float f, __nv_bfloat16& hi, __nv_bfloat16& lo) {
    hi = __float2bfloat16(f);
    lo = __float2bfloat16(f - __bfloat162float(hi));
}

__device__ __forceinline__ uint32_t sptr(const void* p) {
    return (uint32_t)__cvta_generic_to_shared(p);
}

// ---- 1. input normalization ----
__global__ void k_normalize(const float* __restrict__ sig,
                            const float* __restrict__ mean,
                            const float* __restrict__ var) {
    int i = blockIdx.x * blockDim.x + threadIdx.x;
    if (i < NV * CIN) {
        int c = i % CIN;
        g_x[i] = (sig[i] - mean[c]) * rsqrtf(var[c]);
    }
}

// ---- 2. barycentric patch gather -> tripled bf16 A' (slots [hi, hi, lo]) ----
__global__ void k_patch(const int* __restrict__ idx,
                        const float* __restrict__ w, int C, int KT) {
    int gw = blockIdx.x * 8 + (threadIdx.x >> 5);
    int lane = threadIdx.x & 31;
    if (gw >= NV * RA) return;
    int v = gw / RA, ra = gw % RA;
    const int*   ip = idx + (size_t)gw * 3;
    const float* wp = w   + (size_t)gw * 3;
    int   i0 = ip[0], i1 = ip[1], i2 = ip[2];
    float w0 = wp[0], w1 = wp[1], w2 = wp[2];
    __nv_bfloat16* row = g_A + (size_t)v * LDA;
    for (int c = lane; c < C; c += 32) {
        float p = w0 * g_x[i0 * C + c] + w1 * g_x[i1 * C + c] + w2 * g_x[i2 * C + c];
        __nv_bfloat16 hi, lo; bfsplit(p, hi, lo);
        int kb = 3 * (ra * C + c);
        row[kb] = hi; row[kb + 1] = hi; row[kb + 2] = lo;
    }
    if (ra == 0) {  // zero K padding (rewritten every launch -> deterministic)
        __nv_bfloat16 z = __float2bfloat16(0.f);
        for (int e = 3 * RA * C + lane; e < KT; e += 32) row[e] = z;
    }
}

// ---- 3. rotated weights -> tripled bf16 B' ([K'][N] layout, slots [hi,lo,hi]) ----
__global__ void k_buildB(const float* __restrict__ W, int C, int KT) {
    int K = RA * C;
    int total = K * NCOL;
    int e = blockIdx.x * blockDim.x + threadIdx.x;
    if (e < total) {
        int k = e / NCOL, n = e % NCOL;
        int ra = k / C, c = k % C;
        int r = ra / AA, a = ra % AA;
        int rot = n / TT;
        int t = n - rot * TT;
        int a2 = (a + rot) & 7;
        float val = W[(((size_t)t * RR + r) * AA + a2) * C + c];
        __nv_bfloat16 hi, lo; bfsplit(val, hi, lo);
        size_t o = (size_t)(3 * k) * LDBC + n;
        g_B[o] = hi; g_B[o + LDBC] = lo; g_B[o + 2 * LDBC] = hi;
    }
    int padElems = (KT - 3 * K) * LDBC;
    __nv_bfloat16 z = __float2bfloat16(0.f);
    for (int p = e; p < padElems; p += gridDim.x * blockDim.x)
        g_B[(size_t)(3 * K) * LDBC + p] = z;
}

// ---- 3b. dense weights -> tripled bf16 B' ----
__global__ void k_buildDense(const float* __restrict__ dw) {
    int e = blockIdx.x * blockDim.x + threadIdx.x;
    if (e >= TT * NV) return;
    int k = e / NV, n = e % NV;
    float val = dw[e];
    __nv_bfloat16 hi, lo; bfsplit(val, hi, lo);
    size_t o = (size_t)(3 * k) * LDBD + n;
    g_Bd[o] = hi; g_Bd[o + LDBD] = lo; g_Bd[o + 2 * LDBD] = hi;
}

// ---- 4. bf16x3 tensor-core GEMM: C = A'(M x KT) @ B'(KT x N) + bias ----
// 256x128x64 block tile, 8 warps (4x2), warp tile 64x64, 3-stage cp.async ring,
// one __syncthreads per chunk, mma m16n8k16 bf16 (32 mma per warp per k16-step).
#define ASTG 32768   // 256 rows x 128B
#define BSTG 16384   // 64 rows x 256B
#define STGSZ (ASTG + BSTG)

template <bool RELU>
__global__ void __launch_bounds__(256, 1)
k_gemm(const __nv_bfloat16* __restrict__ A, int lda,
       const __nv_bfloat16* __restrict__ B, int ldb,
       const float* __restrict__ bias, int biasMod,
       float* __restrict__ C, int ldc, int M, int N, int KT) {
    extern __shared__ char smem[];
    __shared__ float sbias[128];
    int tid = threadIdx.x;
    int bm = blockIdx.y * 256, bn = blockIdx.x * 128;
    int warp = tid >> 5, lane = tid & 31;
    int wm = (warp >> 1) * 64;   // 4 warp rows
    int wn = (warp & 1) * 64;    // 2 warp cols

    if (tid < 128) sbias[tid] = bias[(bn + tid) % biasMod];

    float acc[4][8][4];
#pragma unroll
    for (int i = 0; i < 4; i++)
#pragma unroll
        for (int j = 0; j < 8; j++)
#pragma unroll
            for (int q = 0; q < 4; q++) acc[i][j][q] = 0.f;

    // ---- async loaders (SW128 swizzle: 16B unit u of row r -> (u&8)|((u^r)&7)) ----
    auto copyA = [&](int stage, int k0) {
        int r = tid;   // 256 rows, 128B each
        const __nv_bfloat16* src = A + (size_t)(bm + r) * lda + k0;
        char* dst = smem + stage * STGSZ + r * 128;
#pragma unroll
        for (int u = 0; u < 8; u++) {
            int su = u ^ (r & 7);
            asm volatile("cp.async.cg.shared.global [%0], [%1], 16;"
                         :: "r"(sptr(dst + su * 16)), "l"(src + u * 8));
        }
    };
    auto copyB = [&](int stage, int k0) {
        int r = tid >> 2, ub = (tid & 3) * 4;   // 64 rows, 256B each
        const __nv_bfloat16* src = B + (size_t)(k0 + r) * ldb + bn;
        char* dst = smem + stage * STGSZ + ASTG + r * 256;
#pragma unroll
        for (int i = 0; i < 4; i++) {
            int uu = ub + i, su = (uu & 8) | ((uu ^ r) & 7);
            asm volatile("cp.async.cg.shared.global [%0], [%1], 16;"
                         :: "r"(sptr(dst + su * 16)), "l"(src + uu * 8));
        }
    };

    int niter = KT >> 6;
    copyA(0, 0);  copyB(0, 0);
    asm volatile("cp.async.commit_group;");
    copyA(1, 64); copyB(1, 64);
    asm volatile("cp.async.commit_group;");

    int q = lane >> 3, rr = lane & 7;

    for (int i = 0; i < niter; i++) {
        asm volatile("cp.async.wait_group 1;");
        __syncthreads();

        int pf = i + 2;
        if (pf < niter) {
            int st2 = pf % 3;
            copyA(st2, pf * 64); copyB(st2, pf * 64);
        }
        asm volatile("cp.async.commit_group;");

        int st = i % 3;
        const char* sA = smem + st * STGSZ;
        const char* sB = smem + st * STGSZ + ASTG;
#pragma unroll
        for (int ks = 0; ks < 4; ks++) {
            uint32_t a[4][4], bfr[8][2];
#pragma unroll
            for (int mt = 0; mt < 4; mt++) {
                int m_loc = wm + mt * 16 + (q & 1) * 8 + rr;
                int unit = ks * 2 + (q >> 1);
                int su = unit ^ (m_loc & 7);
                asm volatile("ldmatrix.sync.aligned.m8n8.x4.shared.b16 {%0,%1,%2,%3}, [%4];"
                             : "=r"(a[mt][0]), "=r"(a[mt][1]), "=r"(a[mt][2]), "=r"(a[mt][3])
                             : "r"(sptr(sA + m_loc * 128 + su * 16)));
            }
#pragma unroll
            for (int ntp = 0; ntp < 4; ntp++) {
                int k_loc = ks * 16 + (q & 1) * 8 + rr;
                int unit = (wn >> 3) + ntp * 2 + (q >> 1);
                int su = (unit & 8) | ((unit ^ k_loc) & 7);
                asm volatile("ldmatrix.sync.aligned.m8n8.x4.trans.shared.b16 {%0,%1,%2,%3}, [%4];"
                             : "=r"(bfr[2 * ntp][0]), "=r"(bfr[2 * ntp][1]),
                               "=r"(bfr[2 * ntp + 1][0]), "=r"(bfr[2 * ntp + 1][1])
                             : "r"(sptr(sB + k_loc * 256 + su * 16)));
            }
#pragma unroll
            for (int mt = 0; mt < 4; mt++)
#pragma unroll
                for (int nt = 0; nt < 8; nt++) {
                    asm volatile(
                        "mma.sync.aligned.m16n8k16.row.col.f32.bf16.bf16.f32 "
                        "{%0,%1,%2,%3}, {%4,%5,%6,%7}, {%8,%9}, {%0,%1,%2,%3};"
                        : "+f"(acc[mt][nt][0]), "+f"(acc[mt][nt][1]),
                          "+f"(acc[mt][nt][2]), "+f"(acc[mt][nt][3])
                        : "r"(a[mt][0]), "r"(a[mt][1]), "r"(a[mt][2]), "r"(a[mt][3]),
                          "r"(bfr[nt][0]), "r"(bfr[nt][1]));
                }
        }
    }

    // ---- epilogue: bias from smem, float2 stores (cols even, N even) ----
    int g = lane >> 2, t4 = lane & 3;
#pragma unroll
    for (int mt = 0; mt < 4; mt++) {
#pragma unroll
        for (int nt = 0; nt < 8; nt++) {
            int lcol = wn + nt * 8 + 2 * t4;
            int col = bn + lcol;
            if (col >= N) continue;
            float b0 = sbias[lcol], b1 = sbias[lcol + 1];
            int row0 = bm + wm + mt * 16 + g;
#pragma unroll
            for (int h = 0; h < 2; h++) {
                int r = row0 + h * 8;
                if (r >= M) continue;
                float v0 = acc[mt][nt][h * 2 + 0] + b0;
                float v1 = acc[mt][nt][h * 2 + 1] + b1;
                if (RELU) { v0 = fmaxf(v0, 0.f); v1 = fmaxf(v1, 0.f); }
                *reinterpret_cast<float2*>(C + (size_t)r * ldc + col) = make_float2(v0, v1);
            }
        }
    }
}

// ---- 5. angular max pool + batchnorm -> g_x (fp32) and g_Ax (tripled bf16) ----
__global__ void k_amp_bn(const float* __restrict__ bn_g, const float* __restrict__ bn_b,
                         const float* __restrict__ bn_m, const float* __restrict__ bn_v,
                         int blk) {
    int v = blockIdx.x;
    __shared__ float norms[8];
    __shared__ int nbest;
    int tid = threadIdx.x, lane = tid & 31, w = tid >> 5;
    const float* row = g_conv + (size_t)v * NCOL;
    if (w < 8) {
        float s = 0.f;
        for (int t = lane; t < TT; t += 32) { float x = row[w * TT + t]; s += x * x; }
#pragma unroll
        for (int o = 16; o; o >>= 1) s += __shfl_down_sync(0xffffffffu, s, o);
        if (lane == 0) norms[w] = s;
    }
    __syncthreads();
    if (tid == 0) {
        int best = 0; float bv = norms[0];
#pragma unroll
        for (int n = 1; n < 8; n++)
            if (norms[n] > bv) { bv = norms[n]; best = n; }
        nbest = best;
    }
    __syncthreads();
    if (tid < TT) {
        float x = row[nbest * TT + tid];
        float gg = bn_g[blk * TT + tid], bb = bn_b[blk * TT + tid];
        float mm = bn_m[blk * TT + tid], va = bn_v[blk * TT + tid];
        float y = gg * (x - mm) * rsqrtf(va + 1e-3f) + bb;
        g_x[(size_t)v * TT + tid] = y;
        __nv_bfloat16 hi, lo; bfsplit(y, hi, lo);
        __nv_bfloat16* arow = g_Ax + (size_t)v * LDAX;
        arow[3 * tid] = hi; arow[3 * tid + 1] = hi; arow[3 * tid + 2] = lo;
    }
}

extern "C" void kernel_launch(void* const* d_in, const int* in_sizes, int n_in,
                              void* d_out, int out_size) {
    const float* signal  = (const float*)d_in[0];
    const int*   bc_idx  = (const int*)  d_in[1];
    const float* bc_w    = (const float*)d_in[2];
    const float* nmean   = (const float*)d_in[3];
    const float* nvar    = (const float*)d_in[4];
    const float* w0      = (const float*)d_in[5];
    const float* b0      = (const float*)d_in[6];
    const float* w1      = (const float*)d_in[7];
    const float* b1      = (const float*)d_in[8];
    const float* w2      = (const float*)d_in[9];
    const float* b2      = (const float*)d_in[10];
    const float* bn_g    = (const float*)d_in[11];
    const float* bn_b    = (const float*)d_in[12];
    const float* bn_m    = (const float*)d_in[13];
    const float* bn_v    = (const float*)d_in[14];
    const float* dense_w = (const float*)d_in[15];
    const float* dense_b = (const float*)d_in[16];
    float* out = (float*)d_out;

    const int SMEM = 3 * STGSZ;   // 144KB
    cudaFuncSetAttribute(k_gemm<true>,  cudaFuncAttributeMaxDynamicSharedMemorySize, SMEM);
    cudaFuncSetAttribute(k_gemm<false>, cudaFuncAttributeMaxDynamicSharedMemorySize, SMEM);

    __nv_bfloat16 *p_A, *p_B, *p_Ax, *p_Bd;
    float *p_conv;
    cudaGetSymbolAddress((void**)&p_A, g_A);
    cudaGetSymbolAddress((void**)&p_B, g_B);
    cudaGetSymbolAddress((void**)&p_Ax, g_Ax);
    cudaGetSymbolAddress((void**)&p_Bd, g_Bd);
    cudaGetSymbolAddress((void**)&p_conv, g_conv);

    k_normalize<<<(NV * CIN + 255) / 256, 256>>>(signal, nmean, nvar);

    const float* Ws[3] = {w0, w1, w2};
    const float* bs[3] = {b0, b1, b2};
    const int    Cs[3] = {CIN, TT, TT};
    const int    KTs[3] = {KT_CONV1, KT_CONV23, KT_CONV23};

    int patchGrid = (NV * RA + 7) / 8;
    dim3 convGrid(7, MP / 256);     // N=800 -> 7 col tiles, M -> 27 row tiles

    for (int blk = 0; blk < 3; blk++) {
        int C = Cs[blk];
        int K = RA * C;
        k_patch<<<patchGrid, 256>>>(bc_idx, bc_w, C, KTs[blk]);
        k_buildB<<<(K * NCOL + 255) / 256, 256>>>(Ws[blk], C, KTs[blk]);
        k_gemm<true><<<convGrid, 256, SMEM>>>(p_A, LDA, p_B, LDBC, bs[blk], TT,
                                              p_conv, NCOL, NV, NCOL, KTs[blk]);
        k_amp_bn<<<NV, 256>>>(bn_g, bn_b, bn_m, bn_v, blk);
    }

    // dense head
    k_buildDense<<<(TT * NV + 255) / 256, 256>>>(dense_w);
    dim3 denseGrid(54, MP / 256);   // N=6890 -> 54 col tiles, 27 row tiles
    k_gemm<false><<<denseGrid, 256, SMEM>>>(p_Ax, LDAX, p_Bd, LDBD, dense_b, NV,
                                            out, NV, NV, NV, KT_DENSE);
}

// round 8
// speedup vs baseline: 1.5463x; 1.5463x over previous
#include <cuda_runtime.h>
#include <cuda_bf16.h>
#include <math.h>
#include <stdint.h>

#define NV 6890
#define MP 6912            // padded M (multiple of 96 and 128)
#define CIN 3
#define RR 5
#define AA 8
#define RA 40
#define TT 100
#define NCOL 800
#define LDA 12096          // conv A' row stride (>= 12032)
#define LDBC 896           // conv B' row stride (7*128)
#define LDAX 320           // dense A' row stride
#define LDBD 6912          // dense B' row stride
#define KT_CONV1 384       // 3*120 padded to 64
#define KT_CONV23 12032    // 3*4000 padded to 64
#define KT_DENSE 320       // 3*100 padded to 64

// ---- scratch (device globals, zero-initialized at module load; pads stay zero) ----
__device__ float g_x[NV * TT];
__device__ __nv_bfloat16 g_A [(size_t)MP * LDA];        // A' block layout [Ah|Ah|Al]
__device__ __nv_bfloat16 g_B [(size_t)12096 * LDBC];    // B' block layout [Bh|Bl|Bh] rows
__device__ __nv_bfloat16 g_Ax[(size_t)MP * LDAX];       // dense A' [xh|xh|xl|pad0]
__device__ __nv_bfloat16 g_Bd[(size_t)KT_DENSE * LDBD]; // dense B' [Bh|Bl|Bh|pad0] rows
__device__ float g_conv[NV * NCOL];

__device__ __forceinline__ void bfsplit(float f, __nv_bfloat16& hi, __nv_bfloat16& lo) {
    hi = __float2bfloat16(f);
    lo = __float2bfloat16(f - __bfloat162float(hi));
}

__device__ __forceinline__ uint32_t sptr(const void* p) {
    return (uint32_t)__cvta_generic_to_shared(p);
}

// ---- 1. input normalization ----
__global__ void k_normalize(const float* __restrict__ sig,
                            const float* __restrict__ mean,
                            const float* __restrict__ var) {
    int i = blockIdx.x * blockDim.x + threadIdx.x;
    if (i < NV * CIN) {
        int c = i % CIN;
        g_x[i] = (sig[i] - mean[c]) * rsqrtf(var[c]);
    }
}

// ---- 2. barycentric patch gather -> A' block layout [Ah | Ah | Al] (coalesced) ----
__global__ void k_patch(const int* __restrict__ idx,
                        const float* __restrict__ w, int C, int KT) {
    int gw = blockIdx.x * 8 + (threadIdx.x >> 5);
    int lane = threadIdx.x & 31;
    if (gw >= NV * RA) return;
    int v = gw / RA, ra = gw % RA;
    int K = RA * C;
    const int*   ip = idx + (size_t)gw * 3;
    const float* wp = w   + (size_t)gw * 3;
    int   i0 = ip[0], i1 = ip[1], i2 = ip[2];
    float w0 = wp[0], w1 = wp[1], w2 = wp[2];
    __nv_bfloat16* row = g_A + (size_t)v * LDA;
    for (int c = lane; c < C; c += 32) {
        float p = w0 * g_x[i0 * C + c] + w1 * g_x[i1 * C + c] + w2 * g_x[i2 * C + c];
        __nv_bfloat16 hi, lo; bfsplit(p, hi, lo);
        int k = ra * C + c;
        row[k] = hi; row[K + k] = hi; row[2 * K + k] = lo;
    }
    if (ra == 0) {  // zero K padding tail (rewritten every launch -> deterministic)
        __nv_bfloat16 z = __float2bfloat16(0.f);
        for (int e = 3 * K + lane; e < KT; e += 32) row[e] = z;
    }
}

// ---- 3. rotated weights -> B' block rows [Bh | Bl | Bh] ----
__global__ void k_buildB(const float* __restrict__ W, int C, int KT) {
    int K = RA * C;
    int total = K * NCOL;
    int e = blockIdx.x * blockDim.x + threadIdx.x;
    if (e < total) {
        int k = e / NCOL, n = e % NCOL;
        int ra = k / C, c = k % C;
        int r = ra / AA, a = ra % AA;
        int rot = n / TT;
        int t = n - rot * TT;
        int a2 = (a + rot) & 7;
        float val = W[(((size_t)t * RR + r) * AA + a2) * C + c];
        __nv_bfloat16 hi, lo; bfsplit(val, hi, lo);
        g_B[(size_t)k * LDBC + n] = hi;
        g_B[(size_t)(K + k) * LDBC + n] = lo;
        g_B[(size_t)(2 * K + k) * LDBC + n] = hi;
    }
    int padElems = (KT - 3 * K) * LDBC;
    __nv_bfloat16 z = __float2bfloat16(0.f);
    for (int p = e; p < padElems; p += gridDim.x * blockDim.x)
        g_B[(size_t)(3 * K) * LDBC + p] = z;
}

// ---- 3b. dense weights -> B' block rows [Bh | Bl | Bh] (pad rows stay zero) ----
__global__ void k_buildDense(const float* __restrict__ dw) {
    int e = blockIdx.x * blockDim.x + threadIdx.x;
    if (e >= TT * NV) return;
    int k = e / NV, n = e % NV;
    float val = dw[e];
    __nv_bfloat16 hi, lo; bfsplit(val, hi, lo);
    g_Bd[(size_t)k * LDBD + n] = hi;
    g_Bd[(size_t)(TT + k) * LDBD + n] = lo;
    g_Bd[(size_t)(2 * TT + k) * LDBD + n] = hi;
}

// ---- 4. bf16x3 tensor-core GEMM: C = A'(M x KT) @ B'(KT x N) + bias ----
// 96x128x64 block tile, 384 threads (12 warps, 3x4), warp tile 32x32,
// 3-stage cp.async ring, one __syncthreads per chunk, 2 CTAs/SM (24 warps).
#define ASTG 12288   // 96 rows x 128B
#define BSTG 16384   // 64 rows x 256B
#define STGSZ (ASTG + BSTG)

template <bool RELU>
__global__ void __launch_bounds__(384, 2)
k_gemm(const __nv_bfloat16* __restrict__ A, int lda,
       const __nv_bfloat16* __restrict__ B, int ldb,
       const float* __restrict__ bias, int biasMod,
       float* __restrict__ C, int ldc, int M, int N, int KT) {
    extern __shared__ char smem[];
    __shared__ float sbias[128];
    int tid = threadIdx.x;
    int bm = blockIdx.y * 96, bn = blockIdx.x * 128;
    int warp = tid >> 5, lane = tid & 31;
    int wm = (warp >> 2) * 32;   // 3 warp rows
    int wn = (warp & 3) * 32;    // 4 warp cols

    if (tid < 128) sbias[tid] = bias[(bn + tid) % biasMod];

    float acc[2][4][4];
#pragma unroll
    for (int i = 0; i < 2; i++)
#pragma unroll
        for (int j = 0; j < 4; j++)
#pragma unroll
            for (int q = 0; q < 4; q++) acc[i][j][q] = 0.f;

    // ---- async loaders (SW128 swizzle: 16B unit u of row r -> u ^ (r&7) pattern) ----
    auto copyA = [&](int stage, int k0) {
        int r = tid >> 2, u0 = (tid & 3) * 2;    // 96 rows x 8 units / 384 thr = 2 each
        const __nv_bfloat16* src = A + (size_t)(bm + r) * lda + k0;
        char* dst = smem + stage * STGSZ + r * 128;
#pragma unroll
        for (int i = 0; i < 2; i++) {
            int uu = u0 + i, su = uu ^ (r & 7);
            asm volatile("cp.async.cg.shared.global [%0], [%1], 16;"
                         :: "r"(sptr(dst + su * 16)), "l"(src + uu * 8));
        }
    };
    auto copyB = [&](int stage, int k0) {
        if (tid >= 256) return;                  // 64 rows x 16 units / 256 thr = 4 each
        int r = tid >> 2, ub = (tid & 3) * 4;
        const __nv_bfloat16* src = B + (size_t)(k0 + r) * ldb + bn;
        char* dst = smem + stage * STGSZ + ASTG + r * 256;
#pragma unroll
        for (int i = 0; i < 4; i++) {
            int uu = ub + i, su = (uu & 8) | ((uu ^ r) & 7);
            asm volatile("cp.async.cg.shared.global [%0], [%1], 16;"
                         :: "r"(sptr(dst + su * 16)), "l"(src + uu * 8));
        }
    };

    int niter = KT >> 6;
    copyA(0, 0);  copyB(0, 0);
    asm volatile("cp.async.commit_group;");
    copyA(1, 64); copyB(1, 64);
    asm volatile("cp.async.commit_group;");

    int q = lane >> 3, rr = lane & 7;

    for (int i = 0; i < niter; i++) {
        asm volatile("cp.async.wait_group 1;");
        __syncthreads();

        int pf = i + 2;
        if (pf < niter) {
            int st2 = pf % 3;
            copyA(st2, pf * 64); copyB(st2, pf * 64);
        }
        asm volatile("cp.async.commit_group;");

        int st = i % 3;
        const char* sA = smem + st * STGSZ;
        const char* sB = smem + st * STGSZ + ASTG;
#pragma unroll
        for (int ks = 0; ks < 4; ks++) {
            uint32_t a[2][4], bfr[4][2];
#pragma unroll
            for (int mt = 0; mt < 2; mt++) {
                int m_loc = wm + mt * 16 + (q & 1) * 8 + rr;
                int unit = ks * 2 + (q >> 1);
                int su = unit ^ (m_loc & 7);
                asm volatile("ldmatrix.sync.aligned.m8n8.x4.shared.b16 {%0,%1,%2,%3}, [%4];"
                             : "=r"(a[mt][0]), "=r"(a[mt][1]), "=r"(a[mt][2]), "=r"(a[mt][3])
                             : "r"(sptr(sA + m_loc * 128 + su * 16)));
            }
#pragma unroll
            for (int ntp = 0; ntp < 2; ntp++) {
                int k_loc = ks * 16 + (q & 1) * 8 + rr;
                int unit = (wn >> 3) + ntp * 2 + (q >> 1);
                int su = (unit & 8) | ((unit ^ k_loc) & 7);
                asm volatile("ldmatrix.sync.aligned.m8n8.x4.trans.shared.b16 {%0,%1,%2,%3}, [%4];"
                             : "=r"(bfr[2 * ntp][0]), "=r"(bfr[2 * ntp][1]),
                               "=r"(bfr[2 * ntp + 1][0]), "=r"(bfr[2 * ntp + 1][1])
                             : "r"(sptr(sB + k_loc * 256 + su * 16)));
            }
#pragma unroll
            for (int mt = 0; mt < 2; mt++)
#pragma unroll
                for (int nt = 0; nt < 4; nt++) {
                    asm volatile(
                        "mma.sync.aligned.m16n8k16.row.col.f32.bf16.bf16.f32 "
                        "{%0,%1,%2,%3}, {%4,%5,%6,%7}, {%8,%9}, {%0,%1,%2,%3};"
                        : "+f"(acc[mt][nt][0]), "+f"(acc[mt][nt][1]),
                          "+f"(acc[mt][nt][2]), "+f"(acc[mt][nt][3])
                        : "r"(a[mt][0]), "r"(a[mt][1]), "r"(a[mt][2]), "r"(a[mt][3]),
                          "r"(bfr[nt][0]), "r"(bfr[nt][1]));
                }
        }
    }

    // ---- epilogue: bias from smem, float2 stores ----
    int g = lane >> 2, t4 = lane & 3;
#pragma unroll
    for (int mt = 0; mt < 2; mt++) {
#pragma unroll
        for (int nt = 0; nt < 4; nt++) {
            int lcol = wn + nt * 8 + 2 * t4;
            int col = bn + lcol;
            if (col >= N) continue;
            float b0 = sbias[lcol], b1 = sbias[lcol + 1];
            int row0 = bm + wm + mt * 16 + g;
#pragma unroll
            for (int h = 0; h < 2; h++) {
                int r = row0 + h * 8;
                if (r >= M) continue;
                float v0 = acc[mt][nt][h * 2 + 0] + b0;
                float v1 = acc[mt][nt][h * 2 + 1] + b1;
                if (RELU) { v0 = fmaxf(v0, 0.f); v1 = fmaxf(v1, 0.f); }
                *reinterpret_cast<float2*>(C + (size_t)r * ldc + col) = make_float2(v0, v1);
            }
        }
    }
}

// ---- 5. angular max pool + batchnorm -> g_x (fp32) and g_Ax (block layout bf16) ----
__global__ void k_amp_bn(const float* __restrict__ bn_g, const float* __restrict__ bn_b,
                         const float* __restrict__ bn_m, const float* __restrict__ bn_v,
                         int blk) {
    int v = blockIdx.x;
    __shared__ float norms[8];
    __shared__ int nbest;
    int tid = threadIdx.x, lane = tid & 31, w = tid >> 5;
    const float* row = g_conv + (size_t)v * NCOL;
    if (w < 8) {
        float s = 0.f;
        for (int t = lane; t < TT; t += 32) { float x = row[w * TT + t]; s += x * x; }
#pragma unroll
        for (int o = 16; o; o >>= 1) s += __shfl_down_sync(0xffffffffu, s, o);
        if (lane == 0) norms[w] = s;
    }
    __syncthreads();
    if (tid == 0) {
        int best = 0; float bv = norms[0];
#pragma unroll
        for (int n = 1; n < 8; n++)
            if (norms[n] > bv) { bv = norms[n]; best = n; }
        nbest = best;
    }
    __syncthreads();
    if (tid < TT) {
        float x = row[nbest * TT + tid];
        float gg = bn_g[blk * TT + tid], bb = bn_b[blk * TT + tid];
        float mm = bn_m[blk * TT + tid], va = bn_v[blk * TT + tid];
        float y = gg * (x - mm) * rsqrtf(va + 1e-3f) + bb;
        g_x[(size_t)v * TT + tid] = y;
        __nv_bfloat16 hi, lo; bfsplit(y, hi, lo);
        __nv_bfloat16* arow = g_Ax + (size_t)v * LDAX;
        arow[tid] = hi; arow[TT + tid] = hi; arow[2 * TT + tid] = lo;
    }
}

extern "C" void kernel_launch(void* const* d_in, const int* in_sizes, int n_in,
                              void* d_out, int out_size) {
    const float* signal  = (const float*)d_in[0];
    const int*   bc_idx  = (const int*)  d_in[1];
    const float* bc_w    = (const float*)d_in[2];
    const float* nmean   = (const float*)d_in[3];
    const float* nvar    = (const float*)d_in[4];
    const float* w0      = (const float*)d_in[5];
    const float* b0      = (const float*)d_in[6];
    const float* w1      = (const float*)d_in[7];
    const float* b1      = (const float*)d_in[8];
    const float* w2      = (const float*)d_in[9];
    const float* b2      = (const float*)d_in[10];
    const float* bn_g    = (const float*)d_in[11];
    const float* bn_b    = (const float*)d_in[12];
    const float* bn_m    = (const float*)d_in[13];
    const float* bn_v    = (const float*)d_in[14];
    const float* dense_w = (const float*)d_in[15];
    const float* dense_b = (const float*)d_in[16];
    float* out = (float*)d_out;

    const int SMEM = 3 * STGSZ;   // 84KB
    cudaFuncSetAttribute(k_gemm<true>,  cudaFuncAttributeMaxDynamicSharedMemorySize, SMEM);
    cudaFuncSetAttribute(k_gemm<false>, cudaFuncAttributeMaxDynamicSharedMemorySize, SMEM);

    __nv_bfloat16 *p_A, *p_B, *p_Ax, *p_Bd;
    float *p_conv;
    cudaGetSymbolAddress((void**)&p_A, g_A);
    cudaGetSymbolAddress((void**)&p_B, g_B);
    cudaGetSymbolAddress((void**)&p_Ax, g_Ax);
    cudaGetSymbolAddress((void**)&p_Bd, g_Bd);
    cudaGetSymbolAddress((void**)&p_conv, g_conv);

    k_normalize<<<(NV * CIN + 255) / 256, 256>>>(signal, nmean, nvar);

    const float* Ws[3] = {w0, w1, w2};
    const float* bs[3] = {b0, b1, b2};
    const int    Cs[3] = {CIN, TT, TT};
    const int    KTs[3] = {KT_CONV1, KT_CONV23, KT_CONV23};

    int patchGrid = (NV * RA + 7) / 8;
    dim3 convGrid(7, MP / 96);      // N=800 -> 7 col tiles, M -> 72 row tiles

    for (int blk = 0; blk < 3; blk++) {
        int C = Cs[blk];
        int K = RA * C;
        k_patch<<<patchGrid, 256>>>(bc_idx, bc_w, C, KTs[blk]);
        k_buildB<<<(K * NCOL + 255) / 256, 256>>>(Ws[blk], C, KTs[blk]);
        k_gemm<true><<<convGrid, 384, SMEM>>>(p_A, LDA, p_B, LDBC, bs[blk], TT,
                                              p_conv, NCOL, NV, NCOL, KTs[blk]);
        k_amp_bn<<<NV, 256>>>(bn_g, bn_b, bn_m, bn_v, blk);
    }

    // dense head
    k_buildDense<<<(TT * NV + 255) / 256, 256>>>(dense_w);
    dim3 denseGrid(54, MP / 96);    // N=6890 -> 54 col tiles, 72 row tiles
    k_gemm<false><<<denseGrid, 384, SMEM>>>(p_Ax, LDAX, p_Bd, LDBD, dense_b, NV,
                                            out, NV, NV, NV, KT_DENSE);
}

// round 9
// speedup vs baseline: 1.8895x; 1.2220x over previous
#include <cuda_runtime.h>
#include <cuda_bf16.h>
#include <math.h>
#include <stdint.h>

#define NV 6890
#define MP 6912            // padded M (multiple of 96 and 128)
#define CIN 3
#define RR 5
#define AA 8
#define RA 40
#define TT 100
#define NCOL 800
#define LDA 12096          // conv A' row stride (>= 12032)
#define LDBC 896           // conv B' row stride (7*128)
#define LDAX 320           // dense A' row stride
#define LDBD 6912          // dense B' row stride
#define KT_CONV1 384       // 3*120 padded to 64
#define KT_CONV23 12032    // 3*4000 padded to 64
#define KT_DENSE 320       // 3*100 padded to 64

// ---- scratch (device globals, zero-initialized at module load; pads stay zero) ----
__device__ float g_x[NV * TT];
__device__ __nv_bfloat16 g_A [(size_t)MP * LDA];        // A' block layout [Ah|Ah|Al]
__device__ __nv_bfloat16 g_B [(size_t)12096 * LDBC];    // B' block layout [Bh|Bl|Bh] rows
__device__ __nv_bfloat16 g_Ax[(size_t)MP * LDAX];       // dense A' [xh|xh|xl|pad0]
__device__ __nv_bfloat16 g_Bd[(size_t)KT_DENSE * LDBD]; // dense B' [Bh|Bl|Bh|pad0] rows
__device__ float g_conv[NV * NCOL];

__device__ __forceinline__ void bfsplit(float f, __nv_bfloat16& hi, __nv_bfloat16& lo) {
    hi = __float2bfloat16(f);
    lo = __float2bfloat16(f - __bfloat162float(hi));
}

__device__ __forceinline__ uint32_t sptr(const void* p) {
    return (uint32_t)__cvta_generic_to_shared(p);
}

// ---- 1. input normalization ----
__global__ void k_normalize(const float* __restrict__ sig,
                            const float* __restrict__ mean,
                            const float* __restrict__ var) {
    int i = blockIdx.x * blockDim.x + threadIdx.x;
    if (i < NV * CIN) {
        int c = i % CIN;
        g_x[i] = (sig[i] - mean[c]) * rsqrtf(var[c]);
    }
}

// ---- 2. barycentric patch gather -> A' block layout [Ah | Ah | Al] (coalesced) ----
__global__ void k_patch(const int* __restrict__ idx,
                        const float* __restrict__ w, int C, int KT) {
    int gw = blockIdx.x * 8 + (threadIdx.x >> 5);
    int lane = threadIdx.x & 31;
    if (gw >= NV * RA) return;
    int v = gw / RA, ra = gw % RA;
    int K = RA * C;
    const int*   ip = idx + (size_t)gw * 3;
    const float* wp = w   + (size_t)gw * 3;
    int   i0 = ip[0], i1 = ip[1], i2 = ip[2];
    float w0 = wp[0], w1 = wp[1], w2 = wp[2];
    __nv_bfloat16* row = g_A + (size_t)v * LDA;
    for (int c = lane; c < C; c += 32) {
        float p = w0 * g_x[i0 * C + c] + w1 * g_x[i1 * C + c] + w2 * g_x[i2 * C + c];
        __nv_bfloat16 hi, lo; bfsplit(p, hi, lo);
        int k = ra * C + c;
        row[k] = hi; row[K + k] = hi; row[2 * K + k] = lo;
    }
    if (ra == 0) {  // zero K padding tail
        __nv_bfloat16 z = __float2bfloat16(0.f);
        for (int e = 3 * K + lane; e < KT; e += 32) row[e] = z;
    }
}

// ---- 3. rotated weights -> B' block rows [Bh | Bl | Bh] ----
__global__ void k_buildB(const float* __restrict__ W, int C, int KT) {
    int K = RA * C;
    int total = K * NCOL;
    int e = blockIdx.x * blockDim.x + threadIdx.x;
    if (e < total) {
        int k = e / NCOL, n = e % NCOL;
        int ra = k / C, c = k % C;
        int r = ra / AA, a = ra % AA;
        int rot = n / TT;
        int t = n - rot * TT;
        int a2 = (a + rot) & 7;
        float val = W[(((size_t)t * RR + r) * AA + a2) * C + c];
        __nv_bfloat16 hi, lo; bfsplit(val, hi, lo);
        g_B[(size_t)k * LDBC + n] = hi;
        g_B[(size_t)(K + k) * LDBC + n] = lo;
        g_B[(size_t)(2 * K + k) * LDBC + n] = hi;
    }
    int padElems = (KT - 3 * K) * LDBC;
    __nv_bfloat16 z = __float2bfloat16(0.f);
    for (int p = e; p < padElems; p += gridDim.x * blockDim.x)
        g_B[(size_t)(3 * K) * LDBC + p] = z;
}

// ---- 3b. dense weights -> B' block rows [Bh | Bl | Bh] (pad rows stay zero) ----
__global__ void k_buildDense(const float* __restrict__ dw) {
    int e = blockIdx.x * blockDim.x + threadIdx.x;
    if (e >= TT * NV) return;
    int k = e / NV, n = e % NV;
    float val = dw[e];
    __nv_bfloat16 hi, lo; bfsplit(val, hi, lo);
    g_Bd[(size_t)k * LDBD + n] = hi;
    g_Bd[(size_t)(TT + k) * LDBD + n] = lo;
    g_Bd[(size_t)(2 * TT + k) * LDBD + n] = hi;
}

// ---- 4. bf16x3 tensor-core GEMM: C = A'(M x KT) @ B'(KT x N) + bias ----
// 96x128x64 block tile, 256 threads (8 warps, 2x4), warp tile 48x32,
// 3-stage cp.async ring, ks-level fragment double-buffering, 2 CTAs/SM.
#define ASTG 12288   // 96 rows x 128B
#define BSTG 16384   // 64 rows x 256B
#define STGSZ (ASTG + BSTG)

template <bool RELU>
__global__ void __launch_bounds__(256, 2)
k_gemm(const __nv_bfloat16* __restrict__ A, int lda,
       const __nv_bfloat16* __restrict__ B, int ldb,
       const float* __restrict__ bias, int biasMod,
       float* __restrict__ C, int ldc, int M, int N, int KT) {
    extern __shared__ char smem[];
    __shared__ float sbias[128];
    int tid = threadIdx.x;
    int bm = blockIdx.y * 96, bn = blockIdx.x * 128;
    int warp = tid >> 5, lane = tid & 31;
    int wm = (warp >> 2) * 48;   // 2 warp rows (48 each)
    int wn = (warp & 3) * 32;    // 4 warp cols

    if (tid < 128) sbias[tid] = bias[(bn + tid) % biasMod];

    float acc[3][4][4];
#pragma unroll
    for (int i = 0; i < 3; i++)
#pragma unroll
        for (int j = 0; j < 4; j++)
#pragma unroll
            for (int q = 0; q < 4; q++) acc[i][j][q] = 0.f;

    // ---- async loaders (SW128 swizzle) ----
    auto copyA = [&](int stage, int k0) {
        char* base = smem + stage * STGSZ;
#pragma unroll
        for (int j = 0; j < 3; j++) {        // 96 rows x 8 units = 768 = 3*256
            int idx = tid + 256 * j;
            int r = idx >> 3, u = idx & 7;
            int su = u ^ (r & 7);
            const __nv_bfloat16* src = A + (size_t)(bm + r) * lda + k0 + u * 8;
            asm volatile("cp.async.cg.shared.global [%0], [%1], 16;"
                         :: "r"(sptr(base + r * 128 + su * 16)), "l"(src));
        }
    };
    auto copyB = [&](int stage, int k0) {
        char* base = smem + stage * STGSZ + ASTG;
#pragma unroll
        for (int j = 0; j < 4; j++) {        // 64 rows x 16 units = 1024 = 4*256
            int idx = tid + 256 * j;
            int r = idx >> 4, u = idx & 15;
            int su = (u & 8) | ((u ^ r) & 7);
            const __nv_bfloat16* src = B + (size_t)(k0 + r) * ldb + bn + u * 8;
            asm volatile("cp.async.cg.shared.global [%0], [%1], 16;"
                         :: "r"(sptr(base + r * 256 + su * 16)), "l"(src));
        }
    };

    int niter = KT >> 6;
    copyA(0, 0);  copyB(0, 0);
    asm volatile("cp.async.commit_group;");
    copyA(1, 64); copyB(1, 64);
    asm volatile("cp.async.commit_group;");

    int q = lane >> 3, rr = lane & 7;

    uint32_t af[2][3][4], bf2[2][4][2];

    // fragment loader for one ks into buffer b
    auto ldfrag = [&](const char* sA, const char* sB, int ks, int b) {
#pragma unroll
        for (int mt = 0; mt < 3; mt++) {
            int m_loc = wm + mt * 16 + (q & 1) * 8 + rr;
            int unit = ks * 2 + (q >> 1);
            int su = unit ^ (m_loc & 7);
            asm volatile("ldmatrix.sync.aligned.m8n8.x4.shared.b16 {%0,%1,%2,%3}, [%4];"
                         : "=r"(af[b][mt][0]), "=r"(af[b][mt][1]),
                           "=r"(af[b][mt][2]), "=r"(af[b][mt][3])
                         : "r"(sptr(sA + m_loc * 128 + su * 16)));
        }
#pragma unroll
        for (int ntp = 0; ntp < 2; ntp++) {
            int k_loc = ks * 16 + (q & 1) * 8 + rr;
            int unit = (wn >> 3) + ntp * 2 + (q >> 1);
            int su = (unit & 8) | ((unit ^ k_loc) & 7);
            asm volatile("ldmatrix.sync.aligned.m8n8.x4.trans.shared.b16 {%0,%1,%2,%3}, [%4];"
                         : "=r"(bf2[b][2 * ntp][0]), "=r"(bf2[b][2 * ntp][1]),
                           "=r"(bf2[b][2 * ntp + 1][0]), "=r"(bf2[b][2 * ntp + 1][1])
                         : "r"(sptr(sB + k_loc * 256 + su * 16)));
        }
    };

    for (int i = 0; i < niter; i++) {
        asm volatile("cp.async.wait_group 1;");
        __syncthreads();

        int pf = i + 2;
        if (pf < niter) {
            int st2 = pf % 3;
            copyA(st2, pf * 64); copyB(st2, pf * 64);
        }
        asm volatile("cp.async.commit_group;");

        int st = i % 3;
        const char* sA = smem + st * STGSZ;
        const char* sB = smem + st * STGSZ + ASTG;

        ldfrag(sA, sB, 0, 0);
#pragma unroll
        for (int ks = 0; ks < 4; ks++) {
            int cur = ks & 1;
            if (ks < 3) ldfrag(sA, sB, ks + 1, cur ^ 1);
#pragma unroll
            for (int mt = 0; mt < 3; mt++)
#pragma unroll
                for (int nt = 0; nt < 4; nt++) {
                    asm volatile(
                        "mma.sync.aligned.m16n8k16.row.col.f32.bf16.bf16.f32 "
                        "{%0,%1,%2,%3}, {%4,%5,%6,%7}, {%8,%9}, {%0,%1,%2,%3};"
                        : "+f"(acc[mt][nt][0]), "+f"(acc[mt][nt][1]),
                          "+f"(acc[mt][nt][2]), "+f"(acc[mt][nt][3])
                        : "r"(af[cur][mt][0]), "r"(af[cur][mt][1]),
                          "r"(af[cur][mt][2]), "r"(af[cur][mt][3]),
                          "r"(bf2[cur][nt][0]), "r"(bf2[cur][nt][1]));
                }
        }
    }

    // ---- epilogue: bias from smem, float2 stores ----
    int g = lane >> 2, t4 = lane & 3;
#pragma unroll
    for (int mt = 0; mt < 3; mt++) {
#pragma unroll
        for (int nt = 0; nt < 4; nt++) {
            int lcol = wn + nt * 8 + 2 * t4;
            int col = bn + lcol;
            if (col >= N) continue;
            float b0 = sbias[lcol], b1 = sbias[lcol + 1];
            int row0 = bm + wm + mt * 16 + g;
#pragma unroll
            for (int h = 0; h < 2; h++) {
                int r = row0 + h * 8;
                if (r >= M) continue;
                float v0 = acc[mt][nt][h * 2 + 0] + b0;
                float v1 = acc[mt][nt][h * 2 + 1] + b1;
                if (RELU) { v0 = fmaxf(v0, 0.f); v1 = fmaxf(v1, 0.f); }
                *reinterpret_cast<float2*>(C + (size_t)r * ldc + col) = make_float2(v0, v1);
            }
        }
    }
}

// ---- 5. angular max pool + batchnorm -> g_x (fp32) and g_Ax (block layout bf16) ----
__global__ void k_amp_bn(const float* __restrict__ bn_g, const float* __restrict__ bn_b,
                         const float* __restrict__ bn_m, const float* __restrict__ bn_v,
                         int blk) {
    int v = blockIdx.x;
    __shared__ float norms[8];
    __shared__ int nbest;
    int tid = threadIdx.x, lane = tid & 31, w = tid >> 5;
    const float* row = g_conv + (size_t)v * NCOL;
    if (w < 8) {
        float s = 0.f;
        for (int t = lane; t < TT; t += 32) { float x = row[w * TT + t]; s += x * x; }
#pragma unroll
        for (int o = 16; o; o >>= 1) s += __shfl_down_sync(0xffffffffu, s, o);
        if (lane == 0) norms[w] = s;
    }
    __syncthreads();
    if (tid == 0) {
        int best = 0; float bv = norms[0];
#pragma unroll
        for (int n = 1; n < 8; n++)
            if (norms[n] > bv) { bv = norms[n]; best = n; }
        nbest = best;
    }
    __syncthreads();
    if (tid < TT) {
        float x = row[nbest * TT + tid];
        float gg = bn_g[blk * TT + tid], bb = bn_b[blk * TT + tid];
        float mm = bn_m[blk * TT + tid], va = bn_v[blk * TT + tid];
        float y = gg * (x - mm) * rsqrtf(va + 1e-3f) + bb;
        g_x[(size_t)v * TT + tid] = y;
        __nv_bfloat16 hi, lo; bfsplit(y, hi, lo);
        __nv_bfloat16* arow = g_Ax + (size_t)v * LDAX;
        arow[tid] = hi; arow[TT + tid] = hi; arow[2 * TT + tid] = lo;
    }
}

extern "C" void kernel_launch(void* const* d_in, const int* in_sizes, int n_in,
                              void* d_out, int out_size) {
    const float* signal  = (const float*)d_in[0];
    const int*   bc_idx  = (const int*)  d_in[1];
    const float* bc_w    = (const float*)d_in[2];
    const float* nmean   = (const float*)d_in[3];
    const float* nvar    = (const float*)d_in[4];
    const float* w0      = (const float*)d_in[5];
    const float* b0      = (const float*)d_in[6];
    const float* w1      = (const float*)d_in[7];
    const float* b1      = (const float*)d_in[8];
    const float* w2      = (const float*)d_in[9];
    const float* b2      = (const float*)d_in[10];
    const float* bn_g    = (const float*)d_in[11];
    const float* bn_b    = (const float*)d_in[12];
    const float* bn_m    = (const float*)d_in[13];
    const float* bn_v    = (const float*)d_in[14];
    const float* dense_w = (const float*)d_in[15];
    const float* dense_b = (const float*)d_in[16];
    float* out = (float*)d_out;

    const int SMEM = 3 * STGSZ;   // 84KB
    cudaFuncSetAttribute(k_gemm<true>,  cudaFuncAttributeMaxDynamicSharedMemorySize, SMEM);
    cudaFuncSetAttribute(k_gemm<false>, cudaFuncAttributeMaxDynamicSharedMemorySize, SMEM);

    __nv_bfloat16 *p_A, *p_B, *p_Ax, *p_Bd;
    float *p_conv;
    cudaGetSymbolAddress((void**)&p_A, g_A);
    cudaGetSymbolAddress((void**)&p_B, g_B);
    cudaGetSymbolAddress((void**)&p_Ax, g_Ax);
    cudaGetSymbolAddress((void**)&p_Bd, g_Bd);
    cudaGetSymbolAddress((void**)&p_conv, g_conv);

    k_normalize<<<(NV * CIN + 255) / 256, 256>>>(signal, nmean, nvar);

    const float* Ws[3] = {w0, w1, w2};
    const float* bs[3] = {b0, b1, b2};
    const int    Cs[3] = {CIN, TT, TT};
    const int    KTs[3] = {KT_CONV1, KT_CONV23, KT_CONV23};

    int patchGrid = (NV * RA + 7) / 8;
    dim3 convGrid(7, MP / 96);      // N=800 -> 7 col tiles, M -> 72 row tiles

    for (int blk = 0; blk < 3; blk++) {
        int C = Cs[blk];
        int K = RA * C;
        k_patch<<<patchGrid, 256>>>(bc_idx, bc_w, C, KTs[blk]);
        k_buildB<<<(K * NCOL + 255) / 256, 256>>>(Ws[blk], C, KTs[blk]);
        k_gemm<true><<<convGrid, 256, SMEM>>>(p_A, LDA, p_B, LDBC, bs[blk], TT,
                                              p_conv, NCOL, NV, NCOL, KTs[blk]);
        k_amp_bn<<<NV, 256>>>(bn_g, bn_b, bn_m, bn_v, blk);
    }

    // dense head
    k_buildDense<<<(TT * NV + 255) / 256, 256>>>(dense_w);
    dim3 denseGrid(54, MP / 96);    // N=6890 -> 54 col tiles, 72 row tiles
    k_gemm<false><<<denseGrid, 256, SMEM>>>(p_Ax, LDAX, p_Bd, LDBD, dense_b, NV,
                                            out, NV, NV, NV, KT_DENSE);
}

// round 10
// speedup vs baseline: 4.0702x; 2.1541x over previous
#include <cuda_runtime.h>
#include <cuda_bf16.h>
#include <math.h>
#include <stdint.h>

#define NV 6890
#define MP 6912
#define CIN 3
#define RR 5
#define AA 8
#define TT 100
#define LDAF 12288         // A' row stride: 2*1536 + 3*3072
#define LDAX 320           // dense A' row stride
#define LDBD 6912          // dense B' row stride
#define KT_DENSE 320
#define BTOT 2752512       // total g_B elems

// A region offsets (order f0, f4, f1, f2, f3)
__device__ __constant__ int c_OA[5] = {0, 1536, 3072, 6144, 9216};

// ---- scratch (device globals, zero-initialized; pads stay zero) ----
__device__ float g_x[NV * TT];
__device__ __nv_bfloat16 g_A [(size_t)MP * LDAF];       // per-freq tripled patch DFT
__device__ __nv_bfloat16 g_B [BTOT];                    // per-freq tripled weight DFT
__device__ __nv_bfloat16 g_Ax[(size_t)MP * LDAX];       // dense A'
__device__ __nv_bfloat16 g_Bd[(size_t)KT_DENSE * LDBD]; // dense B'
__device__ float g_cf[(size_t)NV * 1024];               // GEMM outputs per freq

struct SlotTab { int aoff[8], boff[8], coff[8], nw[8], kt[8], ldb[8]; };

__device__ __forceinline__ void bfsplit(float f, __nv_bfloat16& hi, __nv_bfloat16& lo) {
    hi = __float2bfloat16(f);
    lo = __float2bfloat16(f - __bfloat162float(hi));
}
__device__ __forceinline__ uint32_t sptr(const void* p) {
    return (uint32_t)__cvta_generic_to_shared(p);
}

#define SQH 0.70710678118654752f

// ---- 1. input normalization ----
__global__ void k_normalize(const float* __restrict__ sig,
                            const float* __restrict__ mean,
                            const float* __restrict__ var) {
    int i = blockIdx.x * blockDim.x + threadIdx.x;
    if (i < NV * CIN) {
        int c = i % CIN;
        g_x[i] = (sig[i] - mean[c]) * rsqrtf(var[c]);
    }
}

// ---- 2. patch gather + 8-pt angular DFT -> per-freq tripled A' [Ah|Ah|Al] ----
__global__ void k_patch_fft(const int* __restrict__ idx,
                            const float* __restrict__ w, int C, int KTr, int KTc) {
    __shared__ int   sI[8][24];
    __shared__ float sW[8][24];
    int warp = threadIdx.x >> 5, lane = threadIdx.x & 31;
    int gw = blockIdx.x * 8 + warp;
    if (gw >= NV * RR) return;
    int v = gw / RR, r = gw % RR;
    if (lane < 24) {
        sI[warp][lane] = idx[gw * 24 + lane];
        sW[warp][lane] = w[gw * 24 + lane];
    }
    __syncwarp();

    int K1 = RR * C, Kc = 2 * K1;
    __nv_bfloat16* row = g_A + (size_t)v * LDAF;

    for (int c = lane; c < C; c += 32) {
        float p[8];
#pragma unroll
        for (int a = 0; a < 8; a++) {
            p[a] = sW[warp][a*3+0] * g_x[sI[warp][a*3+0] * C + c]
                 + sW[warp][a*3+1] * g_x[sI[warp][a*3+1] * C + c]
                 + sW[warp][a*3+2] * g_x[sI[warp][a*3+2] * C + c];
        }
        float s07 = p[1] - p[3] - p[5] + p[7];
        float s25 = p[1] + p[3] - p[5] - p[7];
        float s16 = p[2] - p[6];
        float d04 = p[0] - p[4];
        float f0 = p[0]+p[1]+p[2]+p[3]+p[4]+p[5]+p[6]+p[7];
        float f4 = p[0]-p[1]+p[2]-p[3]+p[4]-p[5]+p[6]-p[7];
        float re1 = d04 + SQH * s07,  im1 = -(SQH * s25 + s16);
        float re2 = p[0]-p[2]+p[4]-p[6], im2 = -(p[1]-p[3]+p[5]-p[7]);
        float re3 = d04 - SQH * s07,  im3 = s16 - SQH * s25;

        int k = r * C + c;
        __nv_bfloat16 hi, lo;
#define STA(off, K, kk, val) { bfsplit((val), hi, lo); \
        row[(off)+(kk)] = hi; row[(off)+(K)+(kk)] = hi; row[(off)+2*(K)+(kk)] = lo; }
        STA(0,    K1, k, f0);
        STA(1536, K1, k, f4);
        STA(3072, Kc, k, re1); STA(3072, Kc, K1 + k, im1);
        STA(6144, Kc, k, re2); STA(6144, Kc, K1 + k, im2);
        STA(9216, Kc, k, re3); STA(9216, Kc, K1 + k, im3);
#undef STA
    }
    if (r == 0) {   // zero region tails [3K, KT) each launch (deterministic)
        __nv_bfloat16 z = __float2bfloat16(0.f);
        for (int e = 3 * K1 + lane; e < KTr; e += 32) {
            row[e] = z; row[1536 + e] = z;
        }
        for (int e = 3 * Kc + lane; e < KTc; e += 32) {
            row[3072 + e] = z; row[6144 + e] = z; row[9216 + e] = z;
        }
    }
}

// ---- 3a. zero B buffer ----
__global__ void k_zeroB() {
    int i = blockIdx.x * blockDim.x + threadIdx.x;
    uint32_t* p = reinterpret_cast<uint32_t*>(g_B);
    if (i < BTOT / 2) p[i] = 0;
}

// ---- 3b. weight DFT -> per-freq tripled B' [Bh|Bl|Bh] rows ----
// B offsets: f0:0(1536x128) f4:196608 f1:393216(3072x256) f2:1179648 f3:1966080
__global__ void k_buildB_fft(const float* __restrict__ W, int C) {
    int e = blockIdx.x * blockDim.x + threadIdx.x;
    int tot = TT * RR * C;
    if (e >= tot) return;
    int t = e / (RR * C);
    int rc = e % (RR * C);
    int r = rc / C, c = rc % C;
    float p[8];
#pragma unroll
    for (int a = 0; a < 8; a++)
        p[a] = W[(((size_t)t * RR + r) * AA + a) * C + c];
    float s07 = p[1] - p[3] - p[5] + p[7];
    float s25 = p[1] + p[3] - p[5] - p[7];
    float s16 = p[2] - p[6];
    float d04 = p[0] - p[4];
    float f0 = p[0]+p[1]+p[2]+p[3]+p[4]+p[5]+p[6]+p[7];
    float f4 = p[0]-p[1]+p[2]-p[3]+p[4]-p[5]+p[6]-p[7];
    float re1 = d04 + SQH * s07,  im1 = -(SQH * s25 + s16);
    float re2 = p[0]-p[2]+p[4]-p[6], im2 = -(p[1]-p[3]+p[5]-p[7]);
    float re3 = d04 - SQH * s07,  im3 = s16 - SQH * s25;

    int K1 = RR * C, Kc = 2 * K1;
    int k = r * C + c;
    __nv_bfloat16 hi, lo;
#define STB(boff, ldb, K, krow, col, val) { bfsplit((val), hi, lo); \
    g_B[(boff) + (size_t)(krow) * (ldb) + (col)] = hi; \
    g_B[(boff) + (size_t)((K) + (krow)) * (ldb) + (col)] = lo; \
    g_B[(boff) + (size_t)(2*(K) + (krow)) * (ldb) + (col)] = hi; }
    STB(0,      128, K1, k, t, f0);
    STB(196608, 128, K1, k, t, f4);
    // complex f: col t = Re out: rows [Pr:Wr, Pi:Wi]; col 100+t = Im out: [Pr:Wi, Pi:-Wr]
    STB(393216,  256, Kc, k, t, re1);       STB(393216,  256, Kc, K1 + k, t, im1);
    STB(393216,  256, Kc, k, 100 + t, im1); STB(393216,  256, Kc, K1 + k, 100 + t, -re1);
    STB(1179648, 256, Kc, k, t, re2);       STB(1179648, 256, Kc, K1 + k, t, im2);
    STB(1179648, 256, Kc, k, 100 + t, im2); STB(1179648, 256, Kc, K1 + k, 100 + t, -re2);
    STB(1966080, 256, Kc, k, t, re3);       STB(1966080, 256, Kc, K1 + k, t, im3);
    STB(1966080, 256, Kc, k, 100 + t, im3); STB(1966080, 256, Kc, K1 + k, 100 + t, -re3);
#undef STB
}

// ---- 3c. dense weights -> tripled B' [Bh|Bl|Bh] rows ----
__global__ void k_buildDense(const float* __restrict__ dw) {
    int e = blockIdx.x * blockDim.x + threadIdx.x;
    if (e >= TT * NV) return;
    int k = e / NV, n = e % NV;
    __nv_bfloat16 hi, lo; bfsplit(dw[e], hi, lo);
    g_Bd[(size_t)k * LDBD + n] = hi;
    g_Bd[(size_t)(TT + k) * LDBD + n] = lo;
    g_Bd[(size_t)(2 * TT + k) * LDBD + n] = hi;
}

// ======== shared GEMM machinery (96x128x64, 8 warps 2x4, warp 48x32) ========
#define ASTG 12288
#define BSTG 16384
#define STGSZ (ASTG + BSTG)

// ---- 4a. per-frequency conv GEMM (no bias/relu), slot table on blockIdx.x ----
__global__ void __launch_bounds__(256, 2)
k_gemm_f(const __nv_bfloat16* __restrict__ Ab, const __nv_bfloat16* __restrict__ Bb,
         float* __restrict__ Cb, SlotTab st) {
    extern __shared__ char smem[];
    int sx = blockIdx.x;
    const __nv_bfloat16* A = Ab + st.aoff[sx];
    const __nv_bfloat16* B = Bb + st.boff[sx];
    int ldb = st.ldb[sx], KT = st.kt[sx], nw = st.nw[sx], coff = st.coff[sx];

    int tid = threadIdx.x;
    int bm = blockIdx.y * 96;
    int warp = tid >> 5, lane = tid & 31;
    int wm = (warp >> 2) * 48, wn = (warp & 3) * 32;

    float acc[3][4][4];
#pragma unroll
    for (int i = 0; i < 3; i++)
#pragma unroll
        for (int j = 0; j < 4; j++)
#pragma unroll
            for (int q = 0; q < 4; q++) acc[i][j][q] = 0.f;

    auto copyA = [&](int stage, int k0) {
        char* base = smem + stage * STGSZ;
#pragma unroll
        for (int j = 0; j < 3; j++) {
            int idx2 = tid + 256 * j;
            int r = idx2 >> 3, u = idx2 & 7;
            int su = u ^ (r & 7);
            const __nv_bfloat16* src = A + (size_t)(bm + r) * LDAF + k0 + u * 8;
            asm volatile("cp.async.cg.shared.global [%0], [%1], 16;"
                         :: "r"(sptr(base + r * 128 + su * 16)), "l"(src));
        }
    };
    auto copyB = [&](int stage, int k0) {
        char* base = smem + stage * STGSZ + ASTG;
#pragma unroll
        for (int j = 0; j < 4; j++) {
            int idx2 = tid + 256 * j;
            int r = idx2 >> 4, u = idx2 & 15;
            int su = (u & 8) | ((u ^ r) & 7);
            const __nv_bfloat16* src = B + (size_t)(k0 + r) * ldb + u * 8;
            asm volatile("cp.async.cg.shared.global [%0], [%1], 16;"
                         :: "r"(sptr(base + r * 256 + su * 16)), "l"(src));
        }
    };

    int niter = KT >> 6;
    copyA(0, 0);  copyB(0, 0);
    asm volatile("cp.async.commit_group;");
    copyA(1, 64); copyB(1, 64);
    asm volatile("cp.async.commit_group;");

    int q = lane >> 3, rr = lane & 7;
    uint32_t af[2][3][4], bf2[2][4][2];

    auto ldfrag = [&](const char* sA, const char* sB, int ks, int b) {
#pragma unroll
        for (int mt = 0; mt < 3; mt++) {
            int m_loc = wm + mt * 16 + (q & 1) * 8 + rr;
            int unit = ks * 2 + (q >> 1);
            int su = unit ^ (m_loc & 7);
            asm volatile("ldmatrix.sync.aligned.m8n8.x4.shared.b16 {%0,%1,%2,%3}, [%4];"
                         : "=r"(af[b][mt][0]), "=r"(af[b][mt][1]),
                           "=r"(af[b][mt][2]), "=r"(af[b][mt][3])
                         : "r"(sptr(sA + m_loc * 128 + su * 16)));
        }
#pragma unroll
        for (int ntp = 0; ntp < 2; ntp++) {
            int k_loc = ks * 16 + (q & 1) * 8 + rr;
            int unit = (wn >> 3) + ntp * 2 + (q >> 1);
            int su = (unit & 8) | ((unit ^ k_loc) & 7);
            asm volatile("ldmatrix.sync.aligned.m8n8.x4.trans.shared.b16 {%0,%1,%2,%3}, [%4];"
                         : "=r"(bf2[b][2 * ntp][0]), "=r"(bf2[b][2 * ntp][1]),
                           "=r"(bf2[b][2 * ntp + 1][0]), "=r"(bf2[b][2 * ntp + 1][1])
                         : "r"(sptr(sB + k_loc * 256 + su * 16)));
        }
    };

    for (int i = 0; i < niter; i++) {
        asm volatile("cp.async.wait_group 1;");
        __syncthreads();
        int pf = i + 2;
        if (pf < niter) {
            int st2 = pf % 3;
            copyA(st2, pf * 64); copyB(st2, pf * 64);
        }
        asm volatile("cp.async.commit_group;");

        int stg = i % 3;
        const char* sA = smem + stg * STGSZ;
        const char* sB = smem + stg * STGSZ + ASTG;
        ldfrag(sA, sB, 0, 0);
#pragma unroll
        for (int ks = 0; ks < 4; ks++) {
            int cur = ks & 1;
            if (ks < 3) ldfrag(sA, sB, ks + 1, cur ^ 1);
#pragma unroll
            for (int mt = 0; mt < 3; mt++)
#pragma unroll
                for (int nt = 0; nt < 4; nt++) {
                    asm volatile(
                        "mma.sync.aligned.m16n8k16.row.col.f32.bf16.bf16.f32 "
                        "{%0,%1,%2,%3}, {%4,%5,%6,%7}, {%8,%9}, {%0,%1,%2,%3};"
                        : "+f"(acc[mt][nt][0]), "+f"(acc[mt][nt][1]),
                          "+f"(acc[mt][nt][2]), "+f"(acc[mt][nt][3])
                        : "r"(af[cur][mt][0]), "r"(af[cur][mt][1]),
                          "r"(af[cur][mt][2]), "r"(af[cur][mt][3]),
                          "r"(bf2[cur][nt][0]), "r"(bf2[cur][nt][1]));
                }
        }
    }

    int g = lane >> 2, t4 = lane & 3;
#pragma unroll
    for (int mt = 0; mt < 3; mt++) {
#pragma unroll
        for (int nt = 0; nt < 4; nt++) {
            int lcol = wn + nt * 8 + 2 * t4;
            if (lcol >= nw) continue;
            int row0 = bm + wm + mt * 16 + g;
#pragma unroll
            for (int h = 0; h < 2; h++) {
                int r = row0 + h * 8;
                if (r >= NV) continue;
                *reinterpret_cast<float2*>(Cb + (size_t)r * 1024 + coff + lcol) =
                    make_float2(acc[mt][nt][h * 2 + 0], acc[mt][nt][h * 2 + 1]);
            }
        }
    }
}

// ---- 4b. dense GEMM (bias, no relu) — round-9 kernel unchanged ----
__global__ void __launch_bounds__(256, 2)
k_gemm(const __nv_bfloat16* __restrict__ A, int lda,
       const __nv_bfloat16* __restrict__ B, int ldb,
       const float* __restrict__ bias, int biasMod,
       float* __restrict__ C, int ldc, int M, int N, int KT) {
    extern __shared__ char smem[];
    __shared__ float sbias[128];
    int tid = threadIdx.x;
    int bm = blockIdx.y * 96, bn = blockIdx.x * 128;
    int warp = tid >> 5, lane = tid & 31;
    int wm = (warp >> 2) * 48, wn = (warp & 3) * 32;
    if (tid < 128) sbias[tid] = bias[(bn + tid) % biasMod];

    float acc[3][4][4];
#pragma unroll
    for (int i = 0; i < 3; i++)
#pragma unroll
        for (int j = 0; j < 4; j++)
#pragma unroll
            for (int q = 0; q < 4; q++) acc[i][j][q] = 0.f;

    auto copyA = [&](int stage, int k0) {
        char* base = smem + stage * STGSZ;
#pragma unroll
        for (int j = 0; j < 3; j++) {
            int idx2 = tid + 256 * j;
            int r = idx2 >> 3, u = idx2 & 7;
            int su = u ^ (r & 7);
            const __nv_bfloat16* src = A + (size_t)(bm + r) * lda + k0 + u * 8;
            asm volatile("cp.async.cg.shared.global [%0], [%1], 16;"
                         :: "r"(sptr(base + r * 128 + su * 16)), "l"(src));
        }
    };
    auto copyB = [&](int stage, int k0) {
        char* base = smem + stage * STGSZ + ASTG;
#pragma unroll
        for (int j = 0; j < 4; j++) {
            int idx2 = tid + 256 * j;
            int r = idx2 >> 4, u = idx2 & 15;
            int su = (u & 8) | ((u ^ r) & 7);
            const __nv_bfloat16* src = B + (size_t)(k0 + r) * ldb + bn + u * 8;
            asm volatile("cp.async.cg.shared.global [%0], [%1], 16;"
                         :: "r"(sptr(base + r * 256 + su * 16)), "l"(src));
        }
    };

    int niter = KT >> 6;
    copyA(0, 0);  copyB(0, 0);
    asm volatile("cp.async.commit_group;");
    copyA(1, 64); copyB(1, 64);
    asm volatile("cp.async.commit_group;");

    int q = lane >> 3, rr = lane & 7;
    uint32_t af[2][3][4], bf2[2][4][2];
    auto ldfrag = [&](const char* sA, const char* sB, int ks, int b) {
#pragma unroll
        for (int mt = 0; mt < 3; mt++) {
            int m_loc = wm + mt * 16 + (q & 1) * 8 + rr;
            int unit = ks * 2 + (q >> 1);
            int su = unit ^ (m_loc & 7);
            asm volatile("ldmatrix.sync.aligned.m8n8.x4.shared.b16 {%0,%1,%2,%3}, [%4];"
                         : "=r"(af[b][mt][0]), "=r"(af[b][mt][1]),
                           "=r"(af[b][mt][2]), "=r"(af[b][mt][3])
                         : "r"(sptr(sA + m_loc * 128 + su * 16)));
        }
#pragma unroll
        for (int ntp = 0; ntp < 2; ntp++) {
            int k_loc = ks * 16 + (q & 1) * 8 + rr;
            int unit = (wn >> 3) + ntp * 2 + (q >> 1);
            int su = (unit & 8) | ((unit ^ k_loc) & 7);
            asm volatile("ldmatrix.sync.aligned.m8n8.x4.trans.shared.b16 {%0,%1,%2,%3}, [%4];"
                         : "=r"(bf2[b][2 * ntp][0]), "=r"(bf2[b][2 * ntp][1]),
                           "=r"(bf2[b][2 * ntp + 1][0]), "=r"(bf2[b][2 * ntp + 1][1])
                         : "r"(sptr(sB + k_loc * 256 + su * 16)));
        }
    };

    for (int i = 0; i < niter; i++) {
        asm volatile("cp.async.wait_group 1;");
        __syncthreads();
        int pf = i + 2;
        if (pf < niter) {
            int st2 = pf % 3;
            copyA(st2, pf * 64); copyB(st2, pf * 64);
        }
        asm volatile("cp.async.commit_group;");
        int stg = i % 3;
        const char* sA = smem + stg * STGSZ;
        const char* sB = smem + stg * STGSZ + ASTG;
        ldfrag(sA, sB, 0, 0);
#pragma unroll
        for (int ks = 0; ks < 4; ks++) {
            int cur = ks & 1;
            if (ks < 3) ldfrag(sA, sB, ks + 1, cur ^ 1);
#pragma unroll
            for (int mt = 0; mt < 3; mt++)
#pragma unroll
                for (int nt = 0; nt < 4; nt++) {
                    asm volatile(
                        "mma.sync.aligned.m16n8k16.row.col.f32.bf16.bf16.f32 "
                        "{%0,%1,%2,%3}, {%4,%5,%6,%7}, {%8,%9}, {%0,%1,%2,%3};"
                        : "+f"(acc[mt][nt][0]), "+f"(acc[mt][nt][1]),
                          "+f"(acc[mt][nt][2]), "+f"(acc[mt][nt][3])
                        : "r"(af[cur][mt][0]), "r"(af[cur][mt][1]),
                          "r"(af[cur][mt][2]), "r"(af[cur][mt][3]),
                          "r"(bf2[cur][nt][0]), "r"(bf2[cur][nt][1]));
                }
        }
    }

    int g = lane >> 2, t4 = lane & 3;
#pragma unroll
    for (int mt = 0; mt < 3; mt++) {
#pragma unroll
        for (int nt = 0; nt < 4; nt++) {
            int lcol = wn + nt * 8 + 2 * t4;
            int col = bn + lcol;
            if (col >= N) continue;
            float b0 = sbias[lcol], b1 = sbias[lcol + 1];
            int row0 = bm + wm + mt * 16 + g;
#pragma unroll
            for (int h = 0; h < 2; h++) {
                int r = row0 + h * 8;
                if (r >= M) continue;
                *reinterpret_cast<float2*>(C + (size_t)r * ldc + col) =
                    make_float2(acc[mt][nt][h * 2 + 0] + b0, acc[mt][nt][h * 2 + 1] + b1);
            }
        }
    }
}

// ---- 5. IDFT + bias + relu + angular max pool + BN -> g_x, g_Ax ----
__device__ __constant__ float c_COS8[8] = {1.f, SQH, 0.f, -SQH, -1.f, -SQH, 0.f, SQH};
__device__ __constant__ float c_SIN8[8] = {0.f, SQH, 1.f, SQH, 0.f, -SQH, -1.f, -SQH};

__global__ void k_amp_fft(const float* __restrict__ bias,
                          const float* __restrict__ bn_g, const float* __restrict__ bn_b,
                          const float* __restrict__ bn_m, const float* __restrict__ bn_v,
                          int blk) {
    int v = blockIdx.x;
    int tid = threadIdx.x, lane = tid & 31, warp = tid >> 5;
    const float* row = g_cf + (size_t)v * 1024;
    __shared__ float wsum[4][8];
    __shared__ int snbest;

    float y[8];
#pragma unroll
    for (int n = 0; n < 8; n++) y[n] = 0.f;
    if (tid < TT) {
        float c0 = row[tid], c4 = row[128 + tid];
        float cr1 = row[256 + tid], ci1 = row[356 + tid];
        float cr2 = row[512 + tid], ci2 = row[612 + tid];
        float cr3 = row[768 + tid], ci3 = row[868 + tid];
        float b = bias[tid];
#pragma unroll
        for (int n = 0; n < 8; n++) {
            float s = c0 + ((n & 1) ? -c4 : c4)
                + 2.f * (cr1 * c_COS8[n & 7]       - ci1 * c_SIN8[n & 7]
                       + cr2 * c_COS8[(2*n) & 7]   - ci2 * c_SIN8[(2*n) & 7]
                       + cr3 * c_COS8[(3*n) & 7]   - ci3 * c_SIN8[(3*n) & 7]);
            y[n] = fmaxf(0.125f * s + b, 0.f);
        }
    }
    // norms per rotation
    float sq[8];
#pragma unroll
    for (int n = 0; n < 8; n++) {
        sq[n] = y[n] * y[n];
#pragma unroll
        for (int o = 16; o; o >>= 1) sq[n] += __shfl_down_sync(0xffffffffu, sq[n], o);
    }
    if (lane == 0)
#pragma unroll
        for (int n = 0; n < 8; n++) wsum[warp][n] = sq[n];
    __syncthreads();
    if (tid == 0) {
        int best = 0; float bv = -1.f;
#pragma unroll
        for (int n = 0; n < 8; n++) {
            float s = wsum[0][n] + wsum[1][n] + wsum[2][n] + wsum[3][n];
            if (s > bv) { bv = s; best = n; }
        }
        snbest = best;
    }
    __syncthreads();
    if (tid < TT) {
        int b = snbest;
        float x = y[0];
#pragma unroll
        for (int n = 1; n < 8; n++) if (b == n) x = y[n];
        float gg = bn_g[blk * TT + tid], bb = bn_b[blk * TT + tid];
        float mm = bn_m[blk * TT + tid], va = bn_v[blk * TT + tid];
        float yy = gg * (x - mm) * rsqrtf(va + 1e-3f) + bb;
        g_x[(size_t)v * TT + tid] = yy;
        __nv_bfloat16 hi, lo; bfsplit(yy, hi, lo);
        __nv_bfloat16* arow = g_Ax + (size_t)v * LDAX;
        arow[tid] = hi; arow[TT + tid] = hi; arow[2 * TT + tid] = lo;
    }
}

extern "C" void kernel_launch(void* const* d_in, const int* in_sizes, int n_in,
                              void* d_out, int out_size) {
    const float* signal  = (const float*)d_in[0];
    const int*   bc_idx  = (const int*)  d_in[1];
    const float* bc_w    = (const float*)d_in[2];
    const float* nmean   = (const float*)d_in[3];
    const float* nvar    = (const float*)d_in[4];
    const float* w0      = (const float*)d_in[5];
    const float* b0      = (const float*)d_in[6];
    const float* w1      = (const float*)d_in[7];
    const float* b1      = (const float*)d_in[8];
    const float* w2      = (const float*)d_in[9];
    const float* b2      = (const float*)d_in[10];
    const float* bn_g    = (const float*)d_in[11];
    const float* bn_b    = (const float*)d_in[12];
    const float* bn_m    = (const float*)d_in[13];
    const float* bn_v    = (const float*)d_in[14];
    const float* dense_w = (const float*)d_in[15];
    const float* dense_b = (const float*)d_in[16];
    float* out = (float*)d_out;

    const int SMEM = 3 * STGSZ;   // 84KB
    cudaFuncSetAttribute(k_gemm_f, cudaFuncAttributeMaxDynamicSharedMemorySize, SMEM);
    cudaFuncSetAttribute(k_gemm,   cudaFuncAttributeMaxDynamicSharedMemorySize, SMEM);

    __nv_bfloat16 *p_A, *p_B, *p_Ax, *p_Bd;
    float *p_cf;
    cudaGetSymbolAddress((void**)&p_A, g_A);
    cudaGetSymbolAddress((void**)&p_B, g_B);
    cudaGetSymbolAddress((void**)&p_Ax, g_Ax);
    cudaGetSymbolAddress((void**)&p_Bd, g_Bd);
    cudaGetSymbolAddress((void**)&p_cf, g_cf);

    k_normalize<<<(NV * CIN + 255) / 256, 256>>>(signal, nmean, nvar);

    const float* Ws[3] = {w0, w1, w2};
    const float* bs[3] = {b0, b1, b2};
    const int    Cs[3] = {CIN, TT, TT};

    const int OA[5]  = {0, 1536, 3072, 6144, 9216};
    const int OB[5]  = {0, 196608, 393216, 1179648, 1966080};

    for (int blk = 0; blk < 3; blk++) {
        int C = Cs[blk];
        int K1 = RR * C;
        int KTr = ((3 * K1 + 63) / 64) * 64;       // 64 or 1536
        int KTc = ((6 * K1 + 63) / 64) * 64;       // 128 or 3072

        k_patch_fft<<<(NV * RR + 7) / 8, 256>>>(bc_idx, bc_w, C, KTr, KTc);
        k_zeroB<<<(BTOT / 2 + 255) / 256, 256>>>();
        k_buildB_fft<<<(TT * RR * C + 255) / 256, 256>>>(Ws[blk], C);

        SlotTab st;
        // slots: f0, f4, f1a, f1b, f2a, f2b, f3a, f3b
        int fa[8] = {0, 1, 2, 2, 3, 3, 4, 4};
        int bn8[8] = {0, 0, 0, 128, 0, 128, 0, 128};
        int co[8] = {0, 128, 256, 384, 512, 640, 768, 896};
        for (int s = 0; s < 8; s++) {
            int f = fa[s];
            bool cplx = (f >= 2);
            st.aoff[s] = OA[f];
            st.ldb[s]  = cplx ? 256 : 128;
            st.boff[s] = OB[f] + bn8[s];
            st.coff[s] = co[s];
            st.kt[s]   = cplx ? KTc : KTr;
            st.nw[s]   = cplx ? (bn8[s] ? 72 : 128) : 100;
        }
        k_gemm_f<<<dim3(8, MP / 96), 256, SMEM>>>(p_A, p_B, p_cf, st);
        k_amp_fft<<<NV, 128>>>(bs[blk], bn_g, bn_b, bn_m, bn_v, blk);
    }

    // dense head
    k_buildDense<<<(TT * NV + 255) / 256, 256>>>(dense_w);
    dim3 denseGrid(54, MP / 96);
    k_gemm<<<denseGrid, 256, SMEM>>>(p_Ax, LDAX, p_Bd, LDBD, dense_b, NV,
                                     out, NV, NV, NV, KT_DENSE);
}

// round 11
// speedup vs baseline: 4.2643x; 1.0477x over previous
#include <cuda_runtime.h>
#include <cuda_bf16.h>
#include <math.h>
#include <stdint.h>

#define NV 6890
#define MP 6912
#define CIN 3
#define RR 5
#define AA 8
#define TT 100
#define NSLOT 11
#define SLOTA 1536                 // A slot stride (elems)
#define LDAF (NSLOT * SLOTA)       // 16896
#define LDCF 1408                  // g_cf row stride (floats)
#define LDAX 320
#define LDBD 6912
#define KT_DENSE 320
// B region offsets (elems) — disjoint per layer, pads never written (stay 0)
#define OB0 0
#define OB1 90112                  // 11*64*128
#define OB2 2252800                // OB1 + 11*1536*128
#define BTOT 4415488               // OB2 + 11*1536*128

// ---- scratch (device globals, zero-initialized at module load) ----
__device__ float g_x[NV * TT];
__device__ __nv_bfloat16 g_A [(size_t)MP * LDAF];
__device__ __nv_bfloat16 g_B [BTOT];
__device__ __nv_bfloat16 g_Ax[(size_t)MP * LDAX];
__device__ __nv_bfloat16 g_Bd[(size_t)KT_DENSE * LDBD];
__device__ float g_cf[(size_t)NV * LDCF];

__device__ __forceinline__ void bfsplit(float f, __nv_bfloat16& hi, __nv_bfloat16& lo) {
    hi = __float2bfloat16(f);
    lo = __float2bfloat16(f - __bfloat162float(hi));
}
__device__ __forceinline__ uint32_t sptr(const void* p) {
    return (uint32_t)__cvta_generic_to_shared(p);
}

#define SQH 0.70710678118654752f

// ---- 8-pt DFT helper: p[8] -> f0, f4, (re,im) for f=1,2,3 (plain DFT, im = -Σ p sin) ----
__device__ __forceinline__ void dft8(const float* p, float& f0, float& f4,
                                     float* re, float* im) {
    float s07 = p[1] - p[3] - p[5] + p[7];
    float s25 = p[1] + p[3] - p[5] - p[7];
    float s16 = p[2] - p[6];
    float d04 = p[0] - p[4];
    f0 = p[0]+p[1]+p[2]+p[3]+p[4]+p[5]+p[6]+p[7];
    f4 = p[0]-p[1]+p[2]-p[3]+p[4]-p[5]+p[6]-p[7];
    re[0] = d04 + SQH * s07;        im[0] = -(SQH * s25 + s16);
    re[1] = p[0]-p[2]+p[4]-p[6];    im[1] = -(p[1]-p[3]+p[5]-p[7]);
    re[2] = d04 - SQH * s07;        im[2] = s16 - SQH * s25;
}

// ---- fused init: normalize + weight DFT B for 3 layers + dense B, one launch ----
// block ranges: [0,81) norm | [81,87) B0 | [87,283) B1 | [283,479) B2 | [479,3171) dense
__device__ void buildB_dev(const float* __restrict__ W, int C,
                           __nv_bfloat16* __restrict__ Bb, int KT, int e) {
    int tot = TT * RR * C;
    if (e >= tot) return;
    int t = e / (RR * C);
    int rc = e % (RR * C);
    int r = rc / C, c = rc % C;
    float p[8];
#pragma unroll
    for (int a = 0; a < 8; a++)
        p[a] = W[(((size_t)t * RR + r) * AA + a) * C + c];
    float f0, f4, re[3], im[3];
    dft8(p, f0, f4, re, im);
    int K1 = RR * C;
    int k = r * C + c;
    int slotSz = KT * 128;
    __nv_bfloat16 hi, lo;
#define STB(s, val) { bfsplit((val), hi, lo); \
    __nv_bfloat16* b_ = Bb + (size_t)(s) * slotSz + t; \
    b_[(size_t)k * 128] = hi; b_[(size_t)(K1 + k) * 128] = lo; \
    b_[(size_t)(2 * K1 + k) * 128] = hi; }
    STB(0, f0); STB(1, f4);
#pragma unroll
    for (int j = 0; j < 3; j++) {
        int s = 2 + 3 * j;
        STB(s,     re[j]);           // b1 = Wr
        STB(s + 1, im[j] - re[j]);   // b2 = Wi - Wr
        STB(s + 2, re[j] + im[j]);   // b3 = Wr + Wi
    }
#undef STB
}

__global__ void k_init(const float* __restrict__ sig, const float* __restrict__ mean,
                       const float* __restrict__ var,
                       const float* __restrict__ w0, const float* __restrict__ w1,
                       const float* __restrict__ w2, const float* __restrict__ dw) {
    int b = blockIdx.x, tid = threadIdx.x;
    if (b < 81) {
        int i = b * 256 + tid;
        if (i < NV * CIN) {
            int c = i % CIN;
            g_x[i] = (sig[i] - mean[c]) * rsqrtf(var[c]);
        }
    } else if (b < 87) {
        buildB_dev(w0, CIN, g_B + OB0, 64, (b - 81) * 256 + tid);
    } else if (b < 283) {
        buildB_dev(w1, TT, g_B + OB1, 1536, (b - 87) * 256 + tid);
    } else if (b < 479) {
        buildB_dev(w2, TT, g_B + OB2, 1536, (b - 283) * 256 + tid);
    } else {
        int e = (b - 479) * 256 + tid;
        if (e < TT * NV) {
            int k = e / NV, n = e % NV;
            __nv_bfloat16 hi, lo; bfsplit(dw[e], hi, lo);
            g_Bd[(size_t)k * LDBD + n] = hi;
            g_Bd[(size_t)(TT + k) * LDBD + n] = lo;
            g_Bd[(size_t)(2 * TT + k) * LDBD + n] = hi;
        }
    }
}

// ---- patch gather + angular DFT + Karatsuba parts -> 11 tripled A slots [hi,hi,lo] ----
__global__ void k_patch_fft(const int* __restrict__ idx,
                            const float* __restrict__ w, int C, int KT) {
    __shared__ int   sI[8][24];
    __shared__ float sW[8][24];
    int warp = threadIdx.x >> 5, lane = threadIdx.x & 31;
    int gw = blockIdx.x * 8 + warp;
    if (gw >= NV * RR) return;
    int v = gw / RR, r = gw % RR;
    if (lane < 24) {
        sI[warp][lane] = idx[gw * 24 + lane];
        sW[warp][lane] = w[gw * 24 + lane];
    }
    __syncwarp();

    int K1 = RR * C;
    __nv_bfloat16* row = g_A + (size_t)v * LDAF;

    for (int c = lane; c < C; c += 32) {
        float p[8];
#pragma unroll
        for (int a = 0; a < 8; a++) {
            p[a] = sW[warp][a*3+0] * g_x[sI[warp][a*3+0] * C + c]
                 + sW[warp][a*3+1] * g_x[sI[warp][a*3+1] * C + c]
                 + sW[warp][a*3+2] * g_x[sI[warp][a*3+2] * C + c];
        }
        float f0, f4, re[3], im[3];
        dft8(p, f0, f4, re, im);
        int k = r * C + c;
        __nv_bfloat16 hi, lo;
#define STA(s, val) { bfsplit((val), hi, lo); \
        __nv_bfloat16* a_ = row + (s) * SLOTA; \
        a_[k] = hi; a_[K1 + k] = hi; a_[2 * K1 + k] = lo; }
        STA(0, f0); STA(1, f4);
#pragma unroll
        for (int j = 0; j < 3; j++) {
            int s = 2 + 3 * j;
            STA(s,     re[j] - im[j]);   // p1 = Pr - Pi
            STA(s + 1, re[j]);           // p2 = Pr
            STA(s + 2, im[j]);           // p3 = Pi
        }
#undef STA
    }
    if (r == 0) {   // zero slot tails [3K1, KT) each launch (A slots shared across layers)
        __nv_bfloat16 z = __float2bfloat16(0.f);
        for (int e = 3 * K1 + lane; e < KT; e += 32)
#pragma unroll
            for (int s = 0; s < NSLOT; s++) row[s * SLOTA + e] = z;
    }
}

// ======== GEMM engine (96x128x64, 8 warps 2x4, warp 48x32, 3-stage ring) ========
#define ASTG 12288
#define BSTG 16384
#define STGSZ (ASTG + BSTG)

// ---- per-slot conv GEMM: uniform 11 slots, K'=KT, N=100 (tile 128) ----
__global__ void __launch_bounds__(256, 2)
k_gemm_f(const __nv_bfloat16* __restrict__ Ab, const __nv_bfloat16* __restrict__ Bb,
         float* __restrict__ Cb, int KT) {
    extern __shared__ char smem[];
    int sx = blockIdx.x;
    const __nv_bfloat16* A = Ab + sx * SLOTA;
    const __nv_bfloat16* B = Bb + (size_t)sx * KT * 128;

    int tid = threadIdx.x;
    int bm = blockIdx.y * 96;
    int warp = tid >> 5, lane = tid & 31;
    int wm = (warp >> 2) * 48, wn = (warp & 3) * 32;

    float acc[3][4][4];
#pragma unroll
    for (int i = 0; i < 3; i++)
#pragma unroll
        for (int j = 0; j < 4; j++)
#pragma unroll
            for (int q = 0; q < 4; q++) acc[i][j][q] = 0.f;

    auto copyA = [&](int stage, int k0) {
        char* base = smem + stage * STGSZ;
#pragma unroll
        for (int j = 0; j < 3; j++) {
            int idx2 = tid + 256 * j;
            int r = idx2 >> 3, u = idx2 & 7;
            int su = u ^ (r & 7);
            const __nv_bfloat16* src = A + (size_t)(bm + r) * LDAF + k0 + u * 8;
            asm volatile("cp.async.cg.shared.global [%0], [%1], 16;"
                         :: "r"(sptr(base + r * 128 + su * 16)), "l"(src));
        }
    };
    auto copyB = [&](int stage, int k0) {
        char* base = smem + stage * STGSZ + ASTG;
#pragma unroll
        for (int j = 0; j < 4; j++) {
            int idx2 = tid + 256 * j;
            int r = idx2 >> 4, u = idx2 & 15;
            int su = (u & 8) | ((u ^ r) & 7);
            const __nv_bfloat16* src = B + (size_t)(k0 + r) * 128 + u * 8;
            asm volatile("cp.async.cg.shared.global [%0], [%1], 16;"
                         :: "r"(sptr(base + r * 256 + su * 16)), "l"(src));
        }
    };

    int niter = KT >> 6;
    copyA(0, 0);  copyB(0, 0);
    asm volatile("cp.async.commit_group;");
    copyA(1, 64); copyB(1, 64);
    asm volatile("cp.async.commit_group;");

    int q = lane >> 3, rr = lane & 7;
    uint32_t af[2][3][4], bf2[2][4][2];

    auto ldfrag = [&](const char* sA, const char* sB, int ks, int b) {
#pragma unroll
        for (int mt = 0; mt < 3; mt++) {
            int m_loc = wm + mt * 16 + (q & 1) * 8 + rr;
            int unit = ks * 2 + (q >> 1);
            int su = unit ^ (m_loc & 7);
            asm volatile("ldmatrix.sync.aligned.m8n8.x4.shared.b16 {%0,%1,%2,%3}, [%4];"
                         : "=r"(af[b][mt][0]), "=r"(af[b][mt][1]),
                           "=r"(af[b][mt][2]), "=r"(af[b][mt][3])
                         : "r"(sptr(sA + m_loc * 128 + su * 16)));
        }
#pragma unroll
        for (int ntp = 0; ntp < 2; ntp++) {
            int k_loc = ks * 16 + (q & 1) * 8 + rr;
            int unit = (wn >> 3) + ntp * 2 + (q >> 1);
            int su = (unit & 8) | ((unit ^ k_loc) & 7);
            asm volatile("ldmatrix.sync.aligned.m8n8.x4.trans.shared.b16 {%0,%1,%2,%3}, [%4];"
                         : "=r"(bf2[b][2 * ntp][0]), "=r"(bf2[b][2 * ntp][1]),
                           "=r"(bf2[b][2 * ntp + 1][0]), "=r"(bf2[b][2 * ntp + 1][1])
                         : "r"(sptr(sB + k_loc * 256 + su * 16)));
        }
    };

    for (int i = 0; i < niter; i++) {
        asm volatile("cp.async.wait_group 1;");
        __syncthreads();
        int pf = i + 2;
        if (pf < niter) {
            int st2 = pf % 3;
            copyA(st2, pf * 64); copyB(st2, pf * 64);
        }
        asm volatile("cp.async.commit_group;");

        int stg = i % 3;
        const char* sA = smem + stg * STGSZ;
        const char* sB = smem + stg * STGSZ + ASTG;
        ldfrag(sA, sB, 0, 0);
#pragma unroll
        for (int ks = 0; ks < 4; ks++) {
            int cur = ks & 1;
            if (ks < 3) ldfrag(sA, sB, ks + 1, cur ^ 1);
#pragma unroll
            for (int mt = 0; mt < 3; mt++)
#pragma unroll
                for (int nt = 0; nt < 4; nt++) {
                    asm volatile(
                        "mma.sync.aligned.m16n8k16.row.col.f32.bf16.bf16.f32 "
                        "{%0,%1,%2,%3}, {%4,%5,%6,%7}, {%8,%9}, {%0,%1,%2,%3};"
                        : "+f"(acc[mt][nt][0]), "+f"(acc[mt][nt][1]),
                          "+f"(acc[mt][nt][2]), "+f"(acc[mt][nt][3])
                        : "r"(af[cur][mt][0]), "r"(af[cur][mt][1]),
                          "r"(af[cur][mt][2]), "r"(af[cur][mt][3]),
                          "r"(bf2[cur][nt][0]), "r"(bf2[cur][nt][1]));
                }
        }
    }

    int g = lane >> 2, t4 = lane & 3;
    int coff = sx * 128;
#pragma unroll
    for (int mt = 0; mt < 3; mt++) {
#pragma unroll
        for (int nt = 0; nt < 4; nt++) {
            int lcol = wn + nt * 8 + 2 * t4;
            if (lcol >= TT) continue;
            int row0 = bm + wm + mt * 16 + g;
#pragma unroll
            for (int h = 0; h < 2; h++) {
                int r = row0 + h * 8;
                if (r >= NV) continue;
                *reinterpret_cast<float2*>(Cb + (size_t)r * LDCF + coff + lcol) =
                    make_float2(acc[mt][nt][h * 2 + 0], acc[mt][nt][h * 2 + 1]);
            }
        }
    }
}

// ---- dense GEMM (bias) — unchanged engine ----
__global__ void __launch_bounds__(256, 2)
k_gemm(const __nv_bfloat16* __restrict__ A, int lda,
       const __nv_bfloat16* __restrict__ B, int ldb,
       const float* __restrict__ bias, int biasMod,
       float* __restrict__ C, int ldc, int M, int N, int KT) {
    extern __shared__ char smem[];
    __shared__ float sbias[128];
    int tid = threadIdx.x;
    int bm = blockIdx.y * 96, bn = blockIdx.x * 128;
    int warp = tid >> 5, lane = tid & 31;
    int wm = (warp >> 2) * 48, wn = (warp & 3) * 32;
    if (tid < 128) sbias[tid] = bias[(bn + tid) % biasMod];

    float acc[3][4][4];
#pragma unroll
    for (int i = 0; i < 3; i++)
#pragma unroll
        for (int j = 0; j < 4; j++)
#pragma unroll
            for (int q = 0; q < 4; q++) acc[i][j][q] = 0.f;

    auto copyA = [&](int stage, int k0) {
        char* base = smem + stage * STGSZ;
#pragma unroll
        for (int j = 0; j < 3; j++) {
            int idx2 = tid + 256 * j;
            int r = idx2 >> 3, u = idx2 & 7;
            int su = u ^ (r & 7);
            const __nv_bfloat16* src = A + (size_t)(bm + r) * lda + k0 + u * 8;
            asm volatile("cp.async.cg.shared.global [%0], [%1], 16;"
                         :: "r"(sptr(base + r * 128 + su * 16)), "l"(src));
        }
    };
    auto copyB = [&](int stage, int k0) {
        char* base = smem + stage * STGSZ + ASTG;
#pragma unroll
        for (int j = 0; j < 4; j++) {
            int idx2 = tid + 256 * j;
            int r = idx2 >> 4, u = idx2 & 15;
            int su = (u & 8) | ((u ^ r) & 7);
            const __nv_bfloat16* src = B + (size_t)(k0 + r) * ldb + bn + u * 8;
            asm volatile("cp.async.cg.shared.global [%0], [%1], 16;"
                         :: "r"(sptr(base + r * 256 + su * 16)), "l"(src));
        }
    };

    int niter = KT >> 6;
    copyA(0, 0);  copyB(0, 0);
    asm volatile("cp.async.commit_group;");
    copyA(1, 64); copyB(1, 64);
    asm volatile("cp.async.commit_group;");

    int q = lane >> 3, rr = lane & 7;
    uint32_t af[2][3][4], bf2[2][4][2];
    auto ldfrag = [&](const char* sA, const char* sB, int ks, int b) {
#pragma unroll
        for (int mt = 0; mt < 3; mt++) {
            int m_loc = wm + mt * 16 + (q & 1) * 8 + rr;
            int unit = ks * 2 + (q >> 1);
            int su = unit ^ (m_loc & 7);
            asm volatile("ldmatrix.sync.aligned.m8n8.x4.shared.b16 {%0,%1,%2,%3}, [%4];"
                         : "=r"(af[b][mt][0]), "=r"(af[b][mt][1]),
                           "=r"(af[b][mt][2]), "=r"(af[b][mt][3])
                         : "r"(sptr(sA + m_loc * 128 + su * 16)));
        }
#pragma unroll
        for (int ntp = 0; ntp < 2; ntp++) {
            int k_loc = ks * 16 + (q & 1) * 8 + rr;
            int unit = (wn >> 3) + ntp * 2 + (q >> 1);
            int su = (unit & 8) | ((unit ^ k_loc) & 7);
            asm volatile("ldmatrix.sync.aligned.m8n8.x4.trans.shared.b16 {%0,%1,%2,%3}, [%4];"
                         : "=r"(bf2[b][2 * ntp][0]), "=r"(bf2[b][2 * ntp][1]),
                           "=r"(bf2[b][2 * ntp + 1][0]), "=r"(bf2[b][2 * ntp + 1][1])
                         : "r"(sptr(sB + k_loc * 256 + su * 16)));
        }
    };

    for (int i = 0; i < niter; i++) {
        asm volatile("cp.async.wait_group 1;");
        __syncthreads();
        int pf = i + 2;
        if (pf < niter) {
            int st2 = pf % 3;
            copyA(st2, pf * 64); copyB(st2, pf * 64);
        }
        asm volatile("cp.async.commit_group;");
        int stg = i % 3;
        const char* sA = smem + stg * STGSZ;
        const char* sB = smem + stg * STGSZ + ASTG;
        ldfrag(sA, sB, 0, 0);
#pragma unroll
        for (int ks = 0; ks < 4; ks++) {
            int cur = ks & 1;
            if (ks < 3) ldfrag(sA, sB, ks + 1, cur ^ 1);
#pragma unroll
            for (int mt = 0; mt < 3; mt++)
#pragma unroll
                for (int nt = 0; nt < 4; nt++) {
                    asm volatile(
                        "mma.sync.aligned.m16n8k16.row.col.f32.bf16.bf16.f32 "
                        "{%0,%1,%2,%3}, {%4,%5,%6,%7}, {%8,%9}, {%0,%1,%2,%3};"
                        : "+f"(acc[mt][nt][0]), "+f"(acc[mt][nt][1]),
                          "+f"(acc[mt][nt][2]), "+f"(acc[mt][nt][3])
                        : "r"(af[cur][mt][0]), "r"(af[cur][mt][1]),
                          "r"(af[cur][mt][2]), "r"(af[cur][mt][3]),
                          "r"(bf2[cur][nt][0]), "r"(bf2[cur][nt][1]));
                }
        }
    }

    int g = lane >> 2, t4 = lane & 3;
#pragma unroll
    for (int mt = 0; mt < 3; mt++) {
#pragma unroll
        for (int nt = 0; nt < 4; nt++) {
            int lcol = wn + nt * 8 + 2 * t4;
            int col = bn + lcol;
            if (col >= N) continue;
            float b0 = sbias[lcol], b1 = sbias[lcol + 1];
            int row0 = bm + wm + mt * 16 + g;
#pragma unroll
            for (int h = 0; h < 2; h++) {
                int r = row0 + h * 8;
                if (r >= M) continue;
                *reinterpret_cast<float2*>(C + (size_t)r * ldc + col) =
                    make_float2(acc[mt][nt][h * 2 + 0] + b0, acc[mt][nt][h * 2 + 1] + b1);
            }
        }
    }
}

// ---- Karatsuba combine + IDFT + bias + relu + AMP + BN -> g_x, g_Ax ----
__device__ __constant__ float c_COS8[8] = {1.f, SQH, 0.f, -SQH, -1.f, -SQH, 0.f, SQH};
__device__ __constant__ float c_SIN8[8] = {0.f, SQH, 1.f, SQH, 0.f, -SQH, -1.f, -SQH};

__global__ void k_amp_fft(const float* __restrict__ bias,
                          const float* __restrict__ bn_g, const float* __restrict__ bn_b,
                          const float* __restrict__ bn_m, const float* __restrict__ bn_v,
                          int blk) {
    int v = blockIdx.x;
    int tid = threadIdx.x, lane = tid & 31, warp = tid >> 5;
    const float* row = g_cf + (size_t)v * LDCF;
    __shared__ float wsum[4][8];
    __shared__ int snbest;

    float y[8];
#pragma unroll
    for (int n = 0; n < 8; n++) y[n] = 0.f;
    if (tid < TT) {
        float c0 = row[tid], c4 = row[128 + tid];
        float Cr[3], Ci[3];
#pragma unroll
        for (int j = 0; j < 3; j++) {
            int base = (2 + 3 * j) * 128;
            float g1 = row[base + tid], g2 = row[base + 128 + tid], g3 = row[base + 256 + tid];
            Cr[j] = g1 + g3;
            Ci[j] = g1 + g2;
        }
        float b = bias[tid];
#pragma unroll
        for (int n = 0; n < 8; n++) {
            float s = c0 + ((n & 1) ? -c4 : c4)
                + 2.f * (Cr[0] * c_COS8[n & 7]     - Ci[0] * c_SIN8[n & 7]
                       + Cr[1] * c_COS8[(2*n) & 7] - Ci[1] * c_SIN8[(2*n) & 7]
                       + Cr[2] * c_COS8[(3*n) & 7] - Ci[2] * c_SIN8[(3*n) & 7]);
            y[n] = fmaxf(0.125f * s + b, 0.f);
        }
    }
    float sq[8];
#pragma unroll
    for (int n = 0; n < 8; n++) {
        sq[n] = y[n] * y[n];
#pragma unroll
        for (int o = 16; o; o >>= 1) sq[n] += __shfl_down_sync(0xffffffffu, sq[n], o);
    }
    if (lane == 0)
#pragma unroll
        for (int n = 0; n < 8; n++) wsum[warp][n] = sq[n];
    __syncthreads();
    if (tid == 0) {
        int best = 0; float bv = -1.f;
#pragma unroll
        for (int n = 0; n < 8; n++) {
            float s = wsum[0][n] + wsum[1][n] + wsum[2][n] + wsum[3][n];
            if (s > bv) { bv = s; best = n; }
        }
        snbest = best;
    }
    __syncthreads();
    if (tid < TT) {
        int b = snbest;
        float x = y[0];
#pragma unroll
        for (int n = 1; n < 8; n++) if (b == n) x = y[n];
        float gg = bn_g[blk * TT + tid], bb = bn_b[blk * TT + tid];
        float mm = bn_m[blk * TT + tid], va = bn_v[blk * TT + tid];
        float yy = gg * (x - mm) * rsqrtf(va + 1e-3f) + bb;
        g_x[(size_t)v * TT + tid] = yy;
        __nv_bfloat16 hi, lo; bfsplit(yy, hi, lo);
        __nv_bfloat16* arow = g_Ax + (size_t)v * LDAX;
        arow[tid] = hi; arow[TT + tid] = hi; arow[2 * TT + tid] = lo;
    }
}

extern "C" void kernel_launch(void* const* d_in, const int* in_sizes, int n_in,
                              void* d_out, int out_size) {
    const float* signal  = (const float*)d_in[0];
    const int*   bc_idx  = (const int*)  d_in[1];
    const float* bc_w    = (const float*)d_in[2];
    const float* nmean   = (const float*)d_in[3];
    const float* nvar    = (const float*)d_in[4];
    const float* w0      = (const float*)d_in[5];
    const float* b0      = (const float*)d_in[6];
    const float* w1      = (const float*)d_in[7];
    const float* b1      = (const float*)d_in[8];
    const float* w2      = (const float*)d_in[9];
    const float* b2      = (const float*)d_in[10];
    const float* bn_g    = (const float*)d_in[11];
    const float* bn_b    = (const float*)d_in[12];
    const float* bn_m    = (const float*)d_in[13];
    const float* bn_v    = (const float*)d_in[14];
    const float* dense_w = (const float*)d_in[15];
    const float* dense_b = (const float*)d_in[16];
    float* out = (float*)d_out;

    const int SMEM = 3 * STGSZ;   // 84KB
    cudaFuncSetAttribute(k_gemm_f, cudaFuncAttributeMaxDynamicSharedMemorySize, SMEM);
    cudaFuncSetAttribute(k_gemm,   cudaFuncAttributeMaxDynamicSharedMemorySize, SMEM);

    __nv_bfloat16 *p_A, *p_B, *p_Ax, *p_Bd;
    float *p_cf;
    cudaGetSymbolAddress((void**)&p_A, g_A);
    cudaGetSymbolAddress((void**)&p_B, g_B);
    cudaGetSymbolAddress((void**)&p_Ax, g_Ax);
    cudaGetSymbolAddress((void**)&p_Bd, g_Bd);
    cudaGetSymbolAddress((void**)&p_cf, g_cf);

    // one fused init launch: normalize + all weight-side DFT builds
    k_init<<<3171, 256>>>(signal, nmean, nvar, w0, w1, w2, dense_w);

    const float* bs[3] = {b0, b1, b2};
    const int    Cs[3] = {CIN, TT, TT};
    const int    KTs[3] = {64, 1536, 1536};
    const size_t OBs[3] = {OB0, OB1, OB2};

    for (int blk = 0; blk < 3; blk++) {
        k_patch_fft<<<(NV * RR + 7) / 8, 256>>>(bc_idx, bc_w, Cs[blk], KTs[blk]);
        k_gemm_f<<<dim3(NSLOT, MP / 96), 256, SMEM>>>(p_A, p_B + OBs[blk], p_cf, KTs[blk]);
        k_amp_fft<<<NV, 128>>>(bs[blk], bn_g, bn_b, bn_m, bn_v, blk);
    }

    // dense head
    dim3 denseGrid(54, MP / 96);
    k_gemm<<<denseGrid, 256, SMEM>>>(p_Ax, LDAX, p_Bd, LDBD, dense_b, NV,
                                     out, NV, NV, NV, KT_DENSE);
}

// round 12
// speedup vs baseline: 4.3148x; 1.0118x over previous
#include <cuda_runtime.h>
#include <cuda_bf16.h>
#include <math.h>
#include <stdint.h>

#define NV 6890
#define MP 6912
#define CIN 3
#define RR 5
#define AA 8
#define TT 100
#define NSLOT 11
#define SLOTA 1024                 // A slot stride: [Ah | Al], each padded to 512
#define LDAF (NSLOT * SLOTA)       // 11264
#define LDCF 1408                  // g_cf row stride (floats)
#define LDAX 320
#define LDBD 6912
#define KT_DENSE 320
// B regions (elems): layer0 11*3*64*128, layers1/2 11*3*512*128 each
#define OB0 0
#define OB1 270336
#define OB2 2433024
#define BTOT 4595712

// ---- scratch (device globals, zero-initialized at module load) ----
__device__ float g_x[NV * TT];
__device__ __nv_bfloat16 g_A [(size_t)MP * LDAF];
__device__ __nv_bfloat16 g_B [BTOT];
__device__ __nv_bfloat16 g_Ax[(size_t)MP * LDAX];
__device__ __nv_bfloat16 g_Bd[(size_t)KT_DENSE * LDBD];
__device__ float g_cf[(size_t)NV * LDCF];

__device__ __forceinline__ void bfsplit(float f, __nv_bfloat16& hi, __nv_bfloat16& lo) {
    hi = __float2bfloat16(f);
    lo = __float2bfloat16(f - __bfloat162float(hi));
}
__device__ __forceinline__ uint32_t sptr(const void* p) {
    return (uint32_t)__cvta_generic_to_shared(p);
}

#define SQH 0.70710678118654752f

// ---- 8-pt DFT: p[8] -> f0, f4, (re,im) for f=1,2,3 ----
__device__ __forceinline__ void dft8(const float* p, float& f0, float& f4,
                                     float* re, float* im) {
    float s07 = p[1] - p[3] - p[5] + p[7];
    float s25 = p[1] + p[3] - p[5] - p[7];
    float s16 = p[2] - p[6];
    float d04 = p[0] - p[4];
    f0 = p[0]+p[1]+p[2]+p[3]+p[4]+p[5]+p[6]+p[7];
    f4 = p[0]-p[1]+p[2]-p[3]+p[4]-p[5]+p[6]-p[7];
    re[0] = d04 + SQH * s07;        im[0] = -(SQH * s25 + s16);
    re[1] = p[0]-p[2]+p[4]-p[6];    im[1] = -(p[1]-p[3]+p[5]-p[7]);
    re[2] = d04 - SQH * s07;        im[2] = s16 - SQH * s25;
}

// ---- weight DFT -> B slot rows [Bh @k | Bl @HB+k | Bh @2HB+k], Karatsuba combos ----
__device__ void buildB_dev(const float* __restrict__ W, int C,
                           __nv_bfloat16* __restrict__ Bb, int HB, int e) {
    int tot = TT * RR * C;
    if (e >= tot) return;
    int t = e / (RR * C);
    int rc = e % (RR * C);
    int r = rc / C, c = rc % C;
    float p[8];
#pragma unroll
    for (int a = 0; a < 8; a++)
        p[a] = W[(((size_t)t * RR + r) * AA + a) * C + c];
    float f0, f4, re[3], im[3];
    dft8(p, f0, f4, re, im);
    int k = r * C + c;
    int slotSz = 3 * HB * 128;
    __nv_bfloat16 hi, lo;
#define STB(s, val) { bfsplit((val), hi, lo); \
    __nv_bfloat16* b_ = Bb + (size_t)(s) * slotSz + t; \
    b_[(size_t)k * 128] = hi; b_[(size_t)(HB + k) * 128] = lo; \
    b_[(size_t)(2 * HB + k) * 128] = hi; }
    STB(0, f0); STB(1, f4);
#pragma unroll
    for (int j = 0; j < 3; j++) {
        int s = 2 + 3 * j;
        STB(s,     re[j]);           // pairs with p1 = Pr - Pi
        STB(s + 1, im[j] - re[j]);   // pairs with p2 = Pr
        STB(s + 2, re[j] + im[j]);   // pairs with p3 = Pi
    }
#undef STB
}

// ---- fused init: normalize + B DFT (3 layers) + dense B, one launch ----
__global__ void k_init(const float* __restrict__ sig, const float* __restrict__ mean,
                       const float* __restrict__ var,
                       const float* __restrict__ w0, const float* __restrict__ w1,
                       const float* __restrict__ w2, const float* __restrict__ dw) {
    int b = blockIdx.x, tid = threadIdx.x;
    if (b < 81) {
        int i = b * 256 + tid;
        if (i < NV * CIN) {
            int c = i % CIN;
            g_x[i] = (sig[i] - mean[c]) * rsqrtf(var[c]);
        }
    } else if (b < 87) {
        buildB_dev(w0, CIN, g_B + OB0, 64,  (b - 81) * 256 + tid);
    } else if (b < 283) {
        buildB_dev(w1, TT,  g_B + OB1, 512, (b - 87) * 256 + tid);
    } else if (b < 479) {
        buildB_dev(w2, TT,  g_B + OB2, 512, (b - 283) * 256 + tid);
    } else {
        int e = (b - 479) * 256 + tid;
        if (e < TT * NV) {
            int k = e / NV, n = e % NV;
            __nv_bfloat16 hi, lo; bfsplit(dw[e], hi, lo);
            g_Bd[(size_t)k * LDBD + n] = hi;
            g_Bd[(size_t)(TT + k) * LDBD + n] = lo;
            g_Bd[(size_t)(2 * TT + k) * LDBD + n] = hi;
        }
    }
}

// ---- patch gather + DFT + Karatsuba parts -> 11 A slots [Ah(512)|Al(512)] ----
__global__ void k_patch_fft(const int* __restrict__ idx,
                            const float* __restrict__ w, int C, int HB) {
    __shared__ int   sI[8][24];
    __shared__ float sW[8][24];
    int warp = threadIdx.x >> 5, lane = threadIdx.x & 31;
    int gw = blockIdx.x * 8 + warp;
    if (gw >= NV * RR) return;
    int v = gw / RR, r = gw % RR;
    if (lane < 24) {
        sI[warp][lane] = idx[gw * 24 + lane];
        sW[warp][lane] = w[gw * 24 + lane];
    }
    __syncwarp();

    int K1 = RR * C;
    __nv_bfloat16* row = g_A + (size_t)v * LDAF;

    for (int c = lane; c < C; c += 32) {
        float p[8];
#pragma unroll
        for (int a = 0; a < 8; a++) {
            p[a] = sW[warp][a*3+0] * g_x[sI[warp][a*3+0] * C + c]
                 + sW[warp][a*3+1] * g_x[sI[warp][a*3+1] * C + c]
                 + sW[warp][a*3+2] * g_x[sI[warp][a*3+2] * C + c];
        }
        float f0, f4, re[3], im[3];
        dft8(p, f0, f4, re, im);
        int k = r * C + c;
        __nv_bfloat16 hi, lo;
#define STA(s, val) { bfsplit((val), hi, lo); \
        __nv_bfloat16* a_ = row + (s) * SLOTA; \
        a_[k] = hi; a_[HB + k] = lo; }
        STA(0, f0); STA(1, f4);
#pragma unroll
        for (int j = 0; j < 3; j++) {
            int s = 2 + 3 * j;
            STA(s,     re[j] - im[j]);
            STA(s + 1, re[j]);
            STA(s + 2, im[j]);
        }
#undef STA
    }
    if (r == 0) {   // zero pads [K1,HB) in both blocks (slots shared across layers)
        __nv_bfloat16 z = __float2bfloat16(0.f);
        for (int e = K1 + lane; e < HB; e += 32)
#pragma unroll
            for (int s = 0; s < NSLOT; s++) {
                row[s * SLOTA + e] = z;
                row[s * SLOTA + HB + e] = z;
            }
    }
}

// ======== GEMM engine (96x128x64, 8 warps 2x4, warp 48x32, 3-stage ring) ========
#define ASTG 12288
#define BSTG 16384
#define STGSZ (ASTG + BSTG)

// ---- per-slot conv GEMM: logical K' = 3*HB, A chunks walk [Ah, Ah, Al] ----
__global__ void __launch_bounds__(256, 2)
k_gemm_f(const __nv_bfloat16* __restrict__ Ab, const __nv_bfloat16* __restrict__ Bb,
         float* __restrict__ Cb, int nh) {
    extern __shared__ char smem[];
    int sx = blockIdx.x;
    const __nv_bfloat16* A = Ab + sx * SLOTA;
    const __nv_bfloat16* B = Bb + (size_t)sx * (3 * nh * 64) * 128;

    int tid = threadIdx.x;
    int bm = blockIdx.y * 96;
    int warp = tid >> 5, lane = tid & 31;
    int wm = (warp >> 2) * 48, wn = (warp & 3) * 32;

    float acc[3][4][4];
#pragma unroll
    for (int i = 0; i < 3; i++)
#pragma unroll
        for (int j = 0; j < 4; j++)
#pragma unroll
            for (int q = 0; q < 4; q++) acc[i][j][q] = 0.f;

    auto aoffOf = [&](int c) { return ((c < nh) ? c : c - nh) * 64; };

    auto copyA = [&](int stage, int chunk) {
        char* base = smem + stage * STGSZ;
        int k0 = aoffOf(chunk);
#pragma unroll
        for (int j = 0; j < 3; j++) {
            int idx2 = tid + 256 * j;
            int r = idx2 >> 3, u = idx2 & 7;
            int su = u ^ (r & 7);
            const __nv_bfloat16* src = A + (size_t)(bm + r) * LDAF + k0 + u * 8;
            asm volatile("cp.async.cg.shared.global [%0], [%1], 16;"
                         :: "r"(sptr(base + r * 128 + su * 16)), "l"(src));
        }
    };
    auto copyB = [&](int stage, int chunk) {
        char* base = smem + stage * STGSZ + ASTG;
        int k0 = chunk * 64;
#pragma unroll
        for (int j = 0; j < 4; j++) {
            int idx2 = tid + 256 * j;
            int r = idx2 >> 4, u = idx2 & 15;
            int su = (u & 8) | ((u ^ r) & 7);
            const __nv_bfloat16* src = B + (size_t)(k0 + r) * 128 + u * 8;
            asm volatile("cp.async.cg.shared.global [%0], [%1], 16;"
                         :: "r"(sptr(base + r * 256 + su * 16)), "l"(src));
        }
    };

    int niter = 3 * nh;
    copyA(0, 0);  copyB(0, 0);
    asm volatile("cp.async.commit_group;");
    copyA(1, 1);  copyB(1, 1);
    asm volatile("cp.async.commit_group;");

    int q = lane >> 3, rr = lane & 7;
    uint32_t af[2][3][4], bf2[2][4][2];

    auto ldfrag = [&](const char* sA, const char* sB, int ks, int b) {
#pragma unroll
        for (int mt = 0; mt < 3; mt++) {
            int m_loc = wm + mt * 16 + (q & 1) * 8 + rr;
            int unit = ks * 2 + (q >> 1);
            int su = unit ^ (m_loc & 7);
            asm volatile("ldmatrix.sync.aligned.m8n8.x4.shared.b16 {%0,%1,%2,%3}, [%4];"
                         : "=r"(af[b][mt][0]), "=r"(af[b][mt][1]),
                           "=r"(af[b][mt][2]), "=r"(af[b][mt][3])
                         : "r"(sptr(sA + m_loc * 128 + su * 16)));
        }
#pragma unroll
        for (int ntp = 0; ntp < 2; ntp++) {
            int k_loc = ks * 16 + (q & 1) * 8 + rr;
            int unit = (wn >> 3) + ntp * 2 + (q >> 1);
            int su = (unit & 8) | ((unit ^ k_loc) & 7);
            asm volatile("ldmatrix.sync.aligned.m8n8.x4.trans.shared.b16 {%0,%1,%2,%3}, [%4];"
                         : "=r"(bf2[b][2 * ntp][0]), "=r"(bf2[b][2 * ntp][1]),
                           "=r"(bf2[b][2 * ntp + 1][0]), "=r"(bf2[b][2 * ntp + 1][1])
                         : "r"(sptr(sB + k_loc * 256 + su * 16)));
        }
    };

    for (int i = 0; i < niter; i++) {
        asm volatile("cp.async.wait_group 1;");
        __syncthreads();
        int pf = i + 2;
        if (pf < niter) {
            int st2 = pf % 3;
            copyA(st2, pf); copyB(st2, pf);
        }
        asm volatile("cp.async.commit_group;");

        int stg = i % 3;
        const char* sA = smem + stg * STGSZ;
        const char* sB = smem + stg * STGSZ + ASTG;
        ldfrag(sA, sB, 0, 0);
#pragma unroll
        for (int ks = 0; ks < 4; ks++) {
            int cur = ks & 1;
            if (ks < 3) ldfrag(sA, sB, ks + 1, cur ^ 1);
#pragma unroll
            for (int mt = 0; mt < 3; mt++)
#pragma unroll
                for (int nt = 0; nt < 4; nt++) {
                    asm volatile(
                        "mma.sync.aligned.m16n8k16.row.col.f32.bf16.bf16.f32 "
                        "{%0,%1,%2,%3}, {%4,%5,%6,%7}, {%8,%9}, {%0,%1,%2,%3};"
                        : "+f"(acc[mt][nt][0]), "+f"(acc[mt][nt][1]),
                          "+f"(acc[mt][nt][2]), "+f"(acc[mt][nt][3])
                        : "r"(af[cur][mt][0]), "r"(af[cur][mt][1]),
                          "r"(af[cur][mt][2]), "r"(af[cur][mt][3]),
                          "r"(bf2[cur][nt][0]), "r"(bf2[cur][nt][1]));
                }
        }
    }

    int g = lane >> 2, t4 = lane & 3;
    int coff = sx * 128;
#pragma unroll
    for (int mt = 0; mt < 3; mt++) {
#pragma unroll
        for (int nt = 0; nt < 4; nt++) {
            int lcol = wn + nt * 8 + 2 * t4;
            if (lcol >= TT) continue;
            int row0 = bm + wm + mt * 16 + g;
#pragma unroll
            for (int h = 0; h < 2; h++) {
                int r = row0 + h * 8;
                if (r >= NV) continue;
                *reinterpret_cast<float2*>(Cb + (size_t)r * LDCF + coff + lcol) =
                    make_float2(acc[mt][nt][h * 2 + 0], acc[mt][nt][h * 2 + 1]);
            }
        }
    }
}

// ---- dense GEMM (bias) — unchanged engine ----
__global__ void __launch_bounds__(256, 2)
k_gemm(const __nv_bfloat16* __restrict__ A, int lda,
       const __nv_bfloat16* __restrict__ B, int ldb,
       const float* __restrict__ bias, int biasMod,
       float* __restrict__ C, int ldc, int M, int N, int KT) {
    extern __shared__ char smem[];
    __shared__ float sbias[128];
    int tid = threadIdx.x;
    int bm = blockIdx.y * 96, bn = blockIdx.x * 128;
    int warp = tid >> 5, lane = tid & 31;
    int wm = (warp >> 2) * 48, wn = (warp & 3) * 32;
    if (tid < 128) sbias[tid] = bias[(bn + tid) % biasMod];

    float acc[3][4][4];
#pragma unroll
    for (int i = 0; i < 3; i++)
#pragma unroll
        for (int j = 0; j < 4; j++)
#pragma unroll
            for (int q = 0; q < 4; q++) acc[i][j][q] = 0.f;

    auto copyA = [&](int stage, int k0) {
        char* base = smem + stage * STGSZ;
#pragma unroll
        for (int j = 0; j < 3; j++) {
            int idx2 = tid + 256 * j;
            int r = idx2 >> 3, u = idx2 & 7;
            int su = u ^ (r & 7);
            const __nv_bfloat16* src = A + (size_t)(bm + r) * lda + k0 + u * 8;
            asm volatile("cp.async.cg.shared.global [%0], [%1], 16;"
                         :: "r"(sptr(base + r * 128 + su * 16)), "l"(src));
        }
    };
    auto copyB = [&](int stage, int k0) {
        char* base = smem + stage * STGSZ + ASTG;
#pragma unroll
        for (int j = 0; j < 4; j++) {
            int idx2 = tid + 256 * j;
            int r = idx2 >> 4, u = idx2 & 15;
            int su = (u & 8) | ((u ^ r) & 7);
            const __nv_bfloat16* src = B + (size_t)(k0 + r) * ldb + bn + u * 8;
            asm volatile("cp.async.cg.shared.global [%0], [%1], 16;"
                         :: "r"(sptr(base + r * 256 + su * 16)), "l"(src));
        }
    };

    int niter = KT >> 6;
    copyA(0, 0);  copyB(0, 0);
    asm volatile("cp.async.commit_group;");
    copyA(1, 64); copyB(1, 64);
    asm volatile("cp.async.commit_group;");

    int q = lane >> 3, rr = lane & 7;
    uint32_t af[2][3][4], bf2[2][4][2];
    auto ldfrag = [&](const char* sA, const char* sB, int ks, int b) {
#pragma unroll
        for (int mt = 0; mt < 3; mt++) {
            int m_loc = wm + mt * 16 + (q & 1) * 8 + rr;
            int unit = ks * 2 + (q >> 1);
            int su = unit ^ (m_loc & 7);
            asm volatile("ldmatrix.sync.aligned.m8n8.x4.shared.b16 {%0,%1,%2,%3}, [%4];"
                         : "=r"(af[b][mt][0]), "=r"(af[b][mt][1]),
                           "=r"(af[b][mt][2]), "=r"(af[b][mt][3])
                         : "r"(sptr(sA + m_loc * 128 + su * 16)));
        }
#pragma unroll
        for (int ntp = 0; ntp < 2; ntp++) {
            int k_loc = ks * 16 + (q & 1) * 8 + rr;
            int unit = (wn >> 3) + ntp * 2 + (q >> 1);
            int su = (unit & 8) | ((unit ^ k_loc) & 7);
            asm volatile("ldmatrix.sync.aligned.m8n8.x4.trans.shared.b16 {%0,%1,%2,%3}, [%4];"
                         : "=r"(bf2[b][2 * ntp][0]), "=r"(bf2[b][2 * ntp][1]),
                           "=r"(bf2[b][2 * ntp + 1][0]), "=r"(bf2[b][2 * ntp + 1][1])
                         : "r"(sptr(sB + k_loc * 256 + su * 16)));
        }
    };

    for (int i = 0; i < niter; i++) {
        asm volatile("cp.async.wait_group 1;");
        __syncthreads();
        int pf = i + 2;
        if (pf < niter) {
            int st2 = pf % 3;
            copyA(st2, pf * 64); copyB(st2, pf * 64);
        }
        asm volatile("cp.async.commit_group;");
        int stg = i % 3;
        const char* sA = smem + stg * STGSZ;
        const char* sB = smem + stg * STGSZ + ASTG;
        ldfrag(sA, sB, 0, 0);
#pragma unroll
        for (int ks = 0; ks < 4; ks++) {
            int cur = ks & 1;
            if (ks < 3) ldfrag(sA, sB, ks + 1, cur ^ 1);
#pragma unroll
            for (int mt = 0; mt < 3; mt++)
#pragma unroll
                for (int nt = 0; nt < 4; nt++) {
                    asm volatile(
                        "mma.sync.aligned.m16n8k16.row.col.f32.bf16.bf16.f32 "
                        "{%0,%1,%2,%3}, {%4,%5,%6,%7}, {%8,%9}, {%0,%1,%2,%3};"
                        : "+f"(acc[mt][nt][0]), "+f"(acc[mt][nt][1]),
                          "+f"(acc[mt][nt][2]), "+f"(acc[mt][nt][3])
                        : "r"(af[cur][mt][0]), "r"(af[cur][mt][1]),
                          "r"(af[cur][mt][2]), "r"(af[cur][mt][3]),
                          "r"(bf2[cur][nt][0]), "r"(bf2[cur][nt][1]));
                }
        }
    }

    int g = lane >> 2, t4 = lane & 3;
#pragma unroll
    for (int mt = 0; mt < 3; mt++) {
#pragma unroll
        for (int nt = 0; nt < 4; nt++) {
            int lcol = wn + nt * 8 + 2 * t4;
            int col = bn + lcol;
            if (col >= N) continue;
            float b0 = sbias[lcol], b1 = sbias[lcol + 1];
            int row0 = bm + wm + mt * 16 + g;
#pragma unroll
            for (int h = 0; h < 2; h++) {
                int r = row0 + h * 8;
                if (r >= M) continue;
                *reinterpret_cast<float2*>(C + (size_t)r * ldc + col) =
                    make_float2(acc[mt][nt][h * 2 + 0] + b0, acc[mt][nt][h * 2 + 1] + b1);
            }
        }
    }
}

// ---- Karatsuba combine + IDFT + bias + relu + AMP + BN -> g_x, g_Ax ----
__device__ __constant__ float c_COS8[8] = {1.f, SQH, 0.f, -SQH, -1.f, -SQH, 0.f, SQH};
__device__ __constant__ float c_SIN8[8] = {0.f, SQH, 1.f, SQH, 0.f, -SQH, -1.f, -SQH};

__global__ void k_amp_fft(const float* __restrict__ bias,
                          const float* __restrict__ bn_g, const float* __restrict__ bn_b,
                          const float* __restrict__ bn_m, const float* __restrict__ bn_v,
                          int blk) {
    int v = blockIdx.x;
    int tid = threadIdx.x, lane = tid & 31, warp = tid >> 5;
    const float* row = g_cf + (size_t)v * LDCF;
    __shared__ float wsum[4][8];
    __shared__ int snbest;

    float y[8];
#pragma unroll
    for (int n = 0; n < 8; n++) y[n] = 0.f;
    if (tid < TT) {
        float c0 = row[tid], c4 = row[128 + tid];
        float Cr[3], Ci[3];
#pragma unroll
        for (int j = 0; j < 3; j++) {
            int base = (2 + 3 * j) * 128;
            float g1 = row[base + tid], g2 = row[base + 128 + tid], g3 = row[base + 256 + tid];
            Cr[j] = g1 + g3;
            Ci[j] = g1 + g2;
        }
        float b = bias[tid];
#pragma unroll
        for (int n = 0; n < 8; n++) {
            float s = c0 + ((n & 1) ? -c4 : c4)
                + 2.f * (Cr[0] * c_COS8[n & 7]     - Ci[0] * c_SIN8[n & 7]
                       + Cr[1] * c_COS8[(2*n) & 7] - Ci[1] * c_SIN8[(2*n) & 7]
                       + Cr[2] * c_COS8[(3*n) & 7] - Ci[2] * c_SIN8[(3*n) & 7]);
            y[n] = fmaxf(0.125f * s + b, 0.f);
        }
    }
    float sq[8];
#pragma unroll
    for (int n = 0; n < 8; n++) {
        sq[n] = y[n] * y[n];
#pragma unroll
        for (int o = 16; o; o >>= 1) sq[n] += __shfl_down_sync(0xffffffffu, sq[n], o);
    }
    if (lane == 0)
#pragma unroll
        for (int n = 0; n < 8; n++) wsum[warp][n] = sq[n];
    __syncthreads();
    if (tid == 0) {
        int best = 0; float bv = -1.f;
#pragma unroll
        for (int n = 0; n < 8; n++) {
            float s = wsum[0][n] + wsum[1][n] + wsum[2][n] + wsum[3][n];
            if (s > bv) { bv = s; best = n; }
        }
        snbest = best;
    }
    __syncthreads();
    if (tid < TT) {
        int b = snbest;
        float x = y[0];
#pragma unroll
        for (int n = 1; n < 8; n++) if (b == n) x = y[n];
        float gg = bn_g[blk * TT + tid], bb = bn_b[blk * TT + tid];
        float mm = bn_m[blk * TT + tid], va = bn_v[blk * TT + tid];
        float yy = gg * (x - mm) * rsqrtf(va + 1e-3f) + bb;
        g_x[(size_t)v * TT + tid] = yy;
        __nv_bfloat16 hi, lo; bfsplit(yy, hi, lo);
        __nv_bfloat16* arow = g_Ax + (size_t)v * LDAX;
        arow[tid] = hi; arow[TT + tid] = hi; arow[2 * TT + tid] = lo;
    }
}

extern "C" void kernel_launch(void* const* d_in, const int* in_sizes, int n_in,
                              void* d_out, int out_size) {
    const float* signal  = (const float*)d_in[0];
    const int*   bc_idx  = (const int*)  d_in[1];
    const float* bc_w    = (const float*)d_in[2];
    const float* nmean   = (const float*)d_in[3];
    const float* nvar    = (const float*)d_in[4];
    const float* w0      = (const float*)d_in[5];
    const float* b0      = (const float*)d_in[6];
    const float* w1      = (const float*)d_in[7];
    const float* b1      = (const float*)d_in[8];
    const float* w2      = (const float*)d_in[9];
    const float* b2      = (const float*)d_in[10];
    const float* bn_g    = (const float*)d_in[11];
    const float* bn_b    = (const float*)d_in[12];
    const float* bn_m    = (const float*)d_in[13];
    const float* bn_v    = (const float*)d_in[14];
    const float* dense_w = (const float*)d_in[15];
    const float* dense_b = (const float*)d_in[16];
    float* out = (float*)d_out;

    const int SMEM = 3 * STGSZ;   // 84KB
    cudaFuncSetAttribute(k_gemm_f, cudaFuncAttributeMaxDynamicSharedMemorySize, SMEM);
    cudaFuncSetAttribute(k_gemm,   cudaFuncAttributeMaxDynamicSharedMemorySize, SMEM);

    __nv_bfloat16 *p_A, *p_B, *p_Ax, *p_Bd;
    float *p_cf;
    cudaGetSymbolAddress((void**)&p_A, g_A);
    cudaGetSymbolAddress((void**)&p_B, g_B);
    cudaGetSymbolAddress((void**)&p_Ax, g_Ax);
    cudaGetSymbolAddress((void**)&p_Bd, g_Bd);
    cudaGetSymbolAddress((void**)&p_cf, g_cf);

    k_init<<<3171, 256>>>(signal, nmean, nvar, w0, w1, w2, dense_w);

    const float* bs[3] = {b0, b1, b2};
    const int    Cs[3] = {CIN, TT, TT};
    const int    HBs[3] = {64, 512, 512};
    const size_t OBs[3] = {OB0, OB1, OB2};

    for (int blk = 0; blk < 3; blk++) {
        k_patch_fft<<<(NV * RR + 7) / 8, 256>>>(bc_idx, bc_w, Cs[blk], HBs[blk]);
        k_gemm_f<<<dim3(NSLOT, MP / 96), 256, SMEM>>>(p_A, p_B + OBs[blk], p_cf, HBs[blk] / 64);
        k_amp_fft<<<NV, 128>>>(bs[blk], bn_g, bn_b, bn_m, bn_v, blk);
    }

    // dense head
    dim3 denseGrid(54, MP / 96);
    k_gemm<<<denseGrid, 256, SMEM>>>(p_Ax, LDAX, p_Bd, LDBD, dense_b, NV,
                                     out, NV, NV, NV, KT_DENSE);
}